// round 1
// baseline (speedup 1.0000x reference)
#include <cuda_runtime.h>
#include <cuda_bf16.h>
#include <math.h>

// ---------------------------------------------------------------------------
// Problem constants
// ---------------------------------------------------------------------------
#define B_    4
#define S_    2048
#define DM_   1024
#define NH_   16
#define DH_   64
#define ROWS_ (B_ * S_)          // 8192

// ---------------------------------------------------------------------------
// Scratch (device globals: allocation-free per harness rules)
// ---------------------------------------------------------------------------
__device__ float g_Q [ROWS_ * DM_];
__device__ float g_K [ROWS_ * DM_];
__device__ float g_V [ROWS_ * DM_];
__device__ float g_AO[ROWS_ * DM_];

// ===========================================================================
// SGEMM with bias:  C[M,N] = A[M,K] @ W[K,N] + bias[N]
// Tiling: 128x128 block, BK=8, 256 threads, 8x8 per-thread micro-tile,
// double-buffered shared memory, float4 global I/O.
// Requires M%128==0, N%128==0, K%8==0 (true here: 8192/1024/1024).
// ===========================================================================
#define GBM 128
#define GBN 128
#define GBK 8

__global__ __launch_bounds__(256, 2)
void sgemm_bias(const float* __restrict__ A, const float* __restrict__ W,
                const float* __restrict__ bias, float* __restrict__ C,
                int M, int N, int K)
{
    __shared__ float As[2][GBK][GBM];   // transposed A tile
    __shared__ float Bs[2][GBK][GBN];

    const int tid = threadIdx.x;
    const int rowBase = blockIdx.y * GBM;
    const int colBase = blockIdx.x * GBN;

    // A-load mapping: 128 rows x 8 k  = 256 float4
    const int a_row = tid >> 1;
    const int a_k4  = (tid & 1) << 2;
    // B-load mapping: 8 k x 128 cols = 256 float4
    const int b_row = tid >> 5;
    const int b_c4  = (tid & 31) << 2;

    const int ty = tid >> 4;   // 0..15
    const int tx = tid & 15;   // 0..15

    float acc[8][8];
#pragma unroll
    for (int i = 0; i < 8; ++i)
#pragma unroll
        for (int j = 0; j < 8; ++j) acc[i][j] = 0.f;

    const int NK = K / GBK;

    // preload tile 0
    {
        float4 av = *(const float4*)(A + (size_t)(rowBase + a_row) * K + a_k4);
        As[0][a_k4 + 0][a_row] = av.x;
        As[0][a_k4 + 1][a_row] = av.y;
        As[0][a_k4 + 2][a_row] = av.z;
        As[0][a_k4 + 3][a_row] = av.w;
        float4 bv = *(const float4*)(W + (size_t)b_row * N + colBase + b_c4);
        *(float4*)&Bs[0][b_row][b_c4] = bv;
    }
    __syncthreads();

    int cur = 0;
    for (int kt = 0; kt < NK; ++kt) {
        float4 av, bv;
        const bool more = (kt + 1) < NK;
        if (more) {
            const int k0n = (kt + 1) * GBK;
            av = *(const float4*)(A + (size_t)(rowBase + a_row) * K + k0n + a_k4);
            bv = *(const float4*)(W + (size_t)(k0n + b_row) * N + colBase + b_c4);
        }

#pragma unroll
        for (int k = 0; k < GBK; ++k) {
            float4 a0 = *(const float4*)&As[cur][k][ty * 8];
            float4 a1 = *(const float4*)&As[cur][k][ty * 8 + 4];
            float4 b0 = *(const float4*)&Bs[cur][k][tx * 8];
            float4 b1 = *(const float4*)&Bs[cur][k][tx * 8 + 4];
            float af[8] = {a0.x, a0.y, a0.z, a0.w, a1.x, a1.y, a1.z, a1.w};
            float bf[8] = {b0.x, b0.y, b0.z, b0.w, b1.x, b1.y, b1.z, b1.w};
#pragma unroll
            for (int i = 0; i < 8; ++i)
#pragma unroll
                for (int j = 0; j < 8; ++j)
                    acc[i][j] = fmaf(af[i], bf[j], acc[i][j]);
        }

        if (more) {
            const int nxt = cur ^ 1;
            As[nxt][a_k4 + 0][a_row] = av.x;
            As[nxt][a_k4 + 1][a_row] = av.y;
            As[nxt][a_k4 + 2][a_row] = av.z;
            As[nxt][a_k4 + 3][a_row] = av.w;
            *(float4*)&Bs[nxt][b_row][b_c4] = bv;
        }
        __syncthreads();
        cur ^= 1;
    }

    // epilogue: + bias, store
    const int cbase = colBase + tx * 8;
    float bb[8];
#pragma unroll
    for (int j = 0; j < 8; ++j) bb[j] = bias[cbase + j];

#pragma unroll
    for (int i = 0; i < 8; ++i) {
        const size_t row = (size_t)(rowBase + ty * 8 + i);
        float4 o0, o1;
        o0.x = acc[i][0] + bb[0]; o0.y = acc[i][1] + bb[1];
        o0.z = acc[i][2] + bb[2]; o0.w = acc[i][3] + bb[3];
        o1.x = acc[i][4] + bb[4]; o1.y = acc[i][5] + bb[5];
        o1.z = acc[i][6] + bb[6]; o1.w = acc[i][7] + bb[7];
        *(float4*)(C + row * N + cbase)     = o0;
        *(float4*)(C + row * N + cbase + 4) = o1;
    }
}

// ===========================================================================
// Flash attention, fp32.
// Grid: (S/64 = 32, B*H = 64). Block: 256 threads.
// Per CTA: 64 query rows x Dh=64, loop over 32 KV tiles of 64 rows.
// Q^T, K^T, P^T in smem (stride 68: 16B-aligned float4, conflict-light).
// ===========================================================================
#define FSP 68   // padded smem stride for transposed 64-row tiles

__global__ __launch_bounds__(256, 2)
void flash_attn(const float* __restrict__ Qg, const float* __restrict__ Kg,
                const float* __restrict__ Vg, float* __restrict__ Og)
{
    extern __shared__ float sm[];
    float* QsT = sm;                    // 64*FSP  (QsT[d*FSP + q])
    float* KsT = QsT + 64 * FSP;        // 64*FSP  (KsT[d*FSP + k])
    float* PsT = KsT + 64 * FSP;        // 64*FSP  (PsT[k*FSP + q])
    float* Vs  = PsT + 64 * FSP;        // 64*64   (Vs[k*64 + d])
    float* rm  = Vs + 64 * 64;          // 64
    float* rl  = rm + 64;               // 64
    float* rc  = rl + 64;               // 64

    const int tid = threadIdx.x;
    const int bh  = blockIdx.y;
    const int b   = bh >> 4;
    const int h   = bh & 15;
    const int q0  = blockIdx.x * 64;

    const size_t rowStart = (size_t)b * S_;     // global row offset for batch
    const int    colOff   = h * DH_;            // head column offset

    // ---- load Q tile (transposed into QsT) ----
#pragma unroll
    for (int it = 0; it < 4; ++it) {
        const int chunk = tid + it * 256;       // 0..1023 float4 chunks
        const int r  = chunk >> 4;              // 0..63 (row in tile)
        const int d4 = (chunk & 15) << 2;       // 0..60
        float4 v = *(const float4*)(Qg + (rowStart + q0 + r) * DM_ + colOff + d4);
        QsT[(d4 + 0) * FSP + r] = v.x;
        QsT[(d4 + 1) * FSP + r] = v.y;
        QsT[(d4 + 2) * FSP + r] = v.z;
        QsT[(d4 + 3) * FSP + r] = v.w;
    }
    if (tid < 64) { rm[tid] = -INFINITY; rl[tid] = 0.f; }

    const int ty = tid >> 4;    // 0..15 -> q micro-rows ty*4..+3
    const int tx = tid & 15;    // 0..15 -> k (or d) micro-cols tx*4..+3

    float o[16];
#pragma unroll
    for (int i = 0; i < 16; ++i) o[i] = 0.f;

    for (int jt = 0; jt < S_ / 64; ++jt) {
        const int k0 = jt * 64;

        // ---- load K (transposed) and V tiles ----
#pragma unroll
        for (int it = 0; it < 4; ++it) {
            const int chunk = tid + it * 256;
            const int r  = chunk >> 4;
            const int d4 = (chunk & 15) << 2;
            float4 kv = *(const float4*)(Kg + (rowStart + k0 + r) * DM_ + colOff + d4);
            KsT[(d4 + 0) * FSP + r] = kv.x;
            KsT[(d4 + 1) * FSP + r] = kv.y;
            KsT[(d4 + 2) * FSP + r] = kv.z;
            KsT[(d4 + 3) * FSP + r] = kv.w;
            float4 vv = *(const float4*)(Vg + (rowStart + k0 + r) * DM_ + colOff + d4);
            *(float4*)&Vs[r * 64 + d4] = vv;
        }
        __syncthreads();

        // ---- S = Q @ K^T (64x64x64), scaled ----
        float s[16];
#pragma unroll
        for (int i = 0; i < 16; ++i) s[i] = 0.f;
        {
            const float* qa = QsT + ty * 4;
            const float* kb = KsT + tx * 4;
#pragma unroll
            for (int d = 0; d < 64; ++d) {
                float4 a = *(const float4*)(qa + d * FSP);
                float4 c = *(const float4*)(kb + d * FSP);
                float af[4] = {a.x, a.y, a.z, a.w};
                float cf[4] = {c.x, c.y, c.z, c.w};
#pragma unroll
                for (int i = 0; i < 4; ++i)
#pragma unroll
                    for (int j = 0; j < 4; ++j)
                        s[i * 4 + j] = fmaf(af[i], cf[j], s[i * 4 + j]);
            }
        }
        // store S transposed (PsT[k][q]) with 1/sqrt(Dh) scale
#pragma unroll
        for (int j = 0; j < 4; ++j) {
            float4 w;
            w.x = s[0 * 4 + j] * 0.125f;
            w.y = s[1 * 4 + j] * 0.125f;
            w.z = s[2 * 4 + j] * 0.125f;
            w.w = s[3 * 4 + j] * 0.125f;
            *(float4*)&PsT[(tx * 4 + j) * FSP + ty * 4] = w;
        }
        __syncthreads();

        // ---- online softmax: 4 lanes per row ----
        {
            const int r    = tid >> 2;
            const int part = tid & 3;
            float* prow = PsT + r;
            float mloc = -INFINITY;
#pragma unroll
            for (int k = 0; k < 16; ++k)
                mloc = fmaxf(mloc, prow[(part * 16 + k) * FSP]);
            mloc = fmaxf(mloc, __shfl_xor_sync(0xffffffffu, mloc, 1));
            mloc = fmaxf(mloc, __shfl_xor_sync(0xffffffffu, mloc, 2));
            const float mold = rm[r];
            const float mnew = fmaxf(mold, mloc);
            float sum = 0.f;
#pragma unroll
            for (int k = 0; k < 16; ++k) {
                const int kk = part * 16 + k;
                float p = __expf(prow[kk * FSP] - mnew);
                prow[kk * FSP] = p;
                sum += p;
            }
            sum += __shfl_xor_sync(0xffffffffu, sum, 1);
            sum += __shfl_xor_sync(0xffffffffu, sum, 2);
            if (part == 0) {
                const float cc = __expf(mold - mnew);
                rc[r] = cc;
                rm[r] = mnew;
                rl[r] = rl[r] * cc + sum;
            }
        }
        __syncthreads();

        // ---- rescale accumulators, then O += P @ V ----
        {
            float cf[4];
#pragma unroll
            for (int i = 0; i < 4; ++i) cf[i] = rc[ty * 4 + i];
#pragma unroll
            for (int i = 0; i < 4; ++i)
#pragma unroll
                for (int j = 0; j < 4; ++j) o[i * 4 + j] *= cf[i];

            const float* pa = PsT + ty * 4;
            const float* vb = Vs + tx * 4;
#pragma unroll
            for (int k = 0; k < 64; ++k) {
                float4 a = *(const float4*)(pa + k * FSP);
                float4 v = *(const float4*)(vb + k * 64);
                float af[4] = {a.x, a.y, a.z, a.w};
                float vf[4] = {v.x, v.y, v.z, v.w};
#pragma unroll
                for (int i = 0; i < 4; ++i)
#pragma unroll
                    for (int j = 0; j < 4; ++j)
                        o[i * 4 + j] = fmaf(af[i], vf[j], o[i * 4 + j]);
            }
        }
        __syncthreads();   // protect KsT/Vs/PsT for next tile
    }

    // ---- normalize and write out ----
    float inv[4];
#pragma unroll
    for (int i = 0; i < 4; ++i) inv[i] = 1.f / rl[ty * 4 + i];
#pragma unroll
    for (int i = 0; i < 4; ++i) {
        float4 w;
        w.x = o[i * 4 + 0] * inv[i];
        w.y = o[i * 4 + 1] * inv[i];
        w.z = o[i * 4 + 2] * inv[i];
        w.w = o[i * 4 + 3] * inv[i];
        *(float4*)(Og + (rowStart + q0 + ty * 4 + i) * DM_ + colOff + tx * 4) = w;
    }
}

// ===========================================================================
// Launch
// ===========================================================================
extern "C" void kernel_launch(void* const* d_in, const int* in_sizes, int n_in,
                              void* d_out, int out_size)
{
    const float* query = (const float*)d_in[0];
    const float* key   = (const float*)d_in[1];
    const float* value = (const float*)d_in[2];
    const float* Wq    = (const float*)d_in[3];
    const float* bq    = (const float*)d_in[4];
    const float* Wk    = (const float*)d_in[5];
    const float* bk    = (const float*)d_in[6];
    const float* Wv    = (const float*)d_in[7];
    const float* bv    = (const float*)d_in[8];
    const float* Wo    = (const float*)d_in[9];
    const float* bo    = (const float*)d_in[10];
    float* out = (float*)d_out;

    float *pQ, *pK, *pV, *pAO;
    cudaGetSymbolAddress((void**)&pQ,  g_Q);
    cudaGetSymbolAddress((void**)&pK,  g_K);
    cudaGetSymbolAddress((void**)&pV,  g_V);
    cudaGetSymbolAddress((void**)&pAO, g_AO);

    const int M = ROWS_, N = DM_, K = DM_;
    dim3 gGrid(N / GBN, M / GBM);   // (8, 64)
    dim3 gBlk(256);

    sgemm_bias<<<gGrid, gBlk>>>(query, Wq, bq, pQ, M, N, K);
    sgemm_bias<<<gGrid, gBlk>>>(key,   Wk, bk, pK, M, N, K);
    sgemm_bias<<<gGrid, gBlk>>>(value, Wv, bv, pV, M, N, K);

    const int smemFA = (3 * 64 * FSP + 64 * 64 + 3 * 64) * (int)sizeof(float);
    cudaFuncSetAttribute(flash_attn, cudaFuncAttributeMaxDynamicSharedMemorySize, smemFA);
    dim3 aGrid(S_ / 64, B_ * NH_);  // (32, 64)
    flash_attn<<<aGrid, gBlk, smemFA>>>(pQ, pK, pV, pAO);

    sgemm_bias<<<gGrid, gBlk>>>(pAO, Wo, bo, out, M, N, K);
}

// round 3
// speedup vs baseline: 1.3377x; 1.3377x over previous
#include <cuda_runtime.h>
#include <cuda_bf16.h>
#include <math.h>
#include <cstdint>

// ---------------------------------------------------------------------------
// Problem constants
// ---------------------------------------------------------------------------
#define B_    4
#define S_    2048
#define DM_   1024
#define NH_   16
#define DH_   64
#define ROWS_ (B_ * S_)          // 8192

// ---------------------------------------------------------------------------
// Scratch (device globals: allocation-free per harness rules)
// ---------------------------------------------------------------------------
__device__ float g_Q [ROWS_ * DM_];
__device__ float g_K [ROWS_ * DM_];
__device__ float g_V [ROWS_ * DM_];
__device__ float g_AO[ROWS_ * DM_];
__device__ __nv_bfloat16 g_Ahi[ROWS_ * DM_];
__device__ __nv_bfloat16 g_Alo[ROWS_ * DM_];
__device__ __nv_bfloat16 g_Whi[DM_ * DM_];   // transposed: [N][K]
__device__ __nv_bfloat16 g_Wlo[DM_ * DM_];   // transposed: [N][K]

// ===========================================================================
// Generic-PTX helpers (legal on plain sm_103 target: sm_80+ instructions)
// ===========================================================================
__device__ __forceinline__ uint32_t smem_u32(const void* p) {
    uint32_t a;
    asm("{ .reg .u64 t; cvta.to.shared.u64 t, %1; cvt.u32.u64 %0, t; }"
        : "=r"(a) : "l"(p));
    return a;
}

__device__ __forceinline__ void cp16(uint32_t s, const void* g) {
    asm volatile("cp.async.cg.shared.global [%0], [%1], 16;" :: "r"(s), "l"(g));
}
#define CP_COMMIT() asm volatile("cp.async.commit_group;" ::: "memory")
#define CP_WAIT(n)  asm volatile("cp.async.wait_group %0;" :: "n"(n) : "memory")

__device__ __forceinline__ void ldmx4(uint32_t* r, uint32_t addr) {
    asm volatile("ldmatrix.sync.aligned.m8n8.x4.shared.b16 {%0,%1,%2,%3}, [%4];"
                 : "=r"(r[0]), "=r"(r[1]), "=r"(r[2]), "=r"(r[3]) : "r"(addr));
}

__device__ __forceinline__ void mma_bf16(float* d, const uint32_t* a,
                                         const uint32_t* b) {
    asm volatile(
        "mma.sync.aligned.m16n8k16.row.col.f32.bf16.bf16.f32 "
        "{%0,%1,%2,%3}, {%4,%5,%6,%7}, {%8,%9}, {%0,%1,%2,%3};"
        : "+f"(d[0]), "+f"(d[1]), "+f"(d[2]), "+f"(d[3])
        : "r"(a[0]), "r"(a[1]), "r"(a[2]), "r"(a[3]), "r"(b[0]), "r"(b[1]));
}

// ===========================================================================
// Prep kernels: fp32 -> bf16 hi/lo split; W transpose+split
// ===========================================================================
__global__ __launch_bounds__(256)
void split_bf16(const float4* __restrict__ x, __nv_bfloat16* __restrict__ hi,
                __nv_bfloat16* __restrict__ lo, int n4) {
    int i = blockIdx.x * blockDim.x + threadIdx.x;
    if (i >= n4) return;
    float4 v = x[i];
    float f[4] = {v.x, v.y, v.z, v.w};
    __nv_bfloat16 h[4], l[4];
#pragma unroll
    for (int j = 0; j < 4; ++j) {
        h[j] = __float2bfloat16_rn(f[j]);
        l[j] = __float2bfloat16_rn(f[j] - __bfloat162float(h[j]));
    }
    ((__nv_bfloat162*)hi)[i * 2 + 0] = __nv_bfloat162(h[0], h[1]);
    ((__nv_bfloat162*)hi)[i * 2 + 1] = __nv_bfloat162(h[2], h[3]);
    ((__nv_bfloat162*)lo)[i * 2 + 0] = __nv_bfloat162(l[0], l[1]);
    ((__nv_bfloat162*)lo)[i * 2 + 1] = __nv_bfloat162(l[2], l[3]);
}

// W[K][N] fp32 -> Wt hi/lo [N][K] bf16 (tiled transpose)
__global__ __launch_bounds__(256)
void wtsplit(const float* __restrict__ W, __nv_bfloat16* __restrict__ hi,
             __nv_bfloat16* __restrict__ lo) {
    __shared__ float t[32][33];
    const int n0 = blockIdx.x * 32;
    const int k0 = blockIdx.y * 32;
    const int tx = threadIdx.x, ty = threadIdx.y;
#pragma unroll
    for (int i = 0; i < 4; ++i)
        t[ty + i * 8][tx] = W[(size_t)(k0 + ty + i * 8) * DM_ + n0 + tx];
    __syncthreads();
#pragma unroll
    for (int i = 0; i < 4; ++i) {
        float v = t[tx][ty + i * 8];
        __nv_bfloat16 h = __float2bfloat16_rn(v);
        __nv_bfloat16 l = __float2bfloat16_rn(v - __bfloat162float(h));
        size_t o = (size_t)(n0 + ty + i * 8) * DM_ + k0 + tx;
        hi[o] = h;
        lo[o] = l;
    }
}

// ===========================================================================
// HMMA GEMM (bf16 hi/lo split x3):  C[M,N] = A @ Wt^T + bias
//   A: [8192][1024] bf16 hi/lo, Wt: [1024(N)][1024(K)] bf16 hi/lo
//   Tile 128x128, BK=32, 256 threads, mma.sync m16n8k16, cp.async dbl-buf.
//   Smem row stride 80B (5x16B) -> conflict-free ldmatrix.
// ===========================================================================
#define BM 128
#define BN 128
#define BK 32
#define NKT (DM_ / BK)            // 32
#define RSTRIDE 80                // bytes per 32-bf16 row in smem
#define TILE_B (128 * RSTRIDE)    // 10240 B
#define STAGE_B (4 * TILE_B)      // Ahi,Alo,Bhi,Blo
#define GEMM_SMEM (2 * STAGE_B)   // 81920 B

__device__ __forceinline__ void load_ktile(uint32_t sb, int kt, int stage,
                                           const __nv_bfloat16* Ahi,
                                           const __nv_bfloat16* Alo,
                                           const __nv_bfloat16* Bhi,
                                           const __nv_bfloat16* Blo,
                                           int rowBase, int colBase) {
    const int tid = threadIdx.x;
    const uint32_t base = sb + stage * STAGE_B;
    const __nv_bfloat16* srcs[4] = {
        Ahi + (size_t)rowBase * DM_ + kt * BK,
        Alo + (size_t)rowBase * DM_ + kt * BK,
        Bhi + (size_t)colBase * DM_ + kt * BK,
        Blo + (size_t)colBase * DM_ + kt * BK};
#pragma unroll
    for (int t = 0; t < 4; ++t) {
#pragma unroll
        for (int i = 0; i < 2; ++i) {
            int c = tid + i * 256;          // 0..511 chunks (128 rows x 4)
            int r = c >> 2, ch = c & 3;
            cp16(base + t * TILE_B + r * RSTRIDE + ch * 16,
                 srcs[t] + (size_t)r * DM_ + ch * 8);
        }
    }
}

__global__ __launch_bounds__(256)
void gemm_mma(const __nv_bfloat16* __restrict__ Ahi,
              const __nv_bfloat16* __restrict__ Alo,
              const __nv_bfloat16* __restrict__ Bhi,
              const __nv_bfloat16* __restrict__ Blo,
              const float* __restrict__ bias, float* __restrict__ C) {
    extern __shared__ char smem[];
    const uint32_t sb = smem_u32(smem);
    const int tid  = threadIdx.x;
    const int wid  = tid >> 5;
    const int lane = tid & 31;
    const int rowBase = blockIdx.y * BM;
    const int colBase = blockIdx.x * BN;

    const int mbase = (wid >> 1) * 32;   // 4 warps along M
    const int nbase = (wid & 1) * 64;    // 2 warps along N

    float acc[2][8][4];
#pragma unroll
    for (int i = 0; i < 2; ++i)
#pragma unroll
        for (int j = 0; j < 8; ++j)
#pragma unroll
            for (int q = 0; q < 4; ++q) acc[i][j][q] = 0.f;

    load_ktile(sb, 0, 0, Ahi, Alo, Bhi, Blo, rowBase, colBase);
    CP_COMMIT();

    // ldmatrix lane addressing (within-tile byte offsets)
    const int a_row = lane & 15;           // m row within 16
    const int a_kh  = (lane >> 4) << 4;    // 0 or 16 bytes (k half)
    const int b_row = ((lane >> 4) & 1) * 8 + (lane & 7); // n row within 16
    const int b_kh  = ((lane >> 3) & 1) << 4;             // 0 or 16 bytes

    for (int kt = 0; kt < NKT; ++kt) {
        const int cur = kt & 1;
        if (kt + 1 < NKT) {
            load_ktile(sb, kt + 1, cur ^ 1, Ahi, Alo, Bhi, Blo, rowBase, colBase);
            CP_COMMIT();
            CP_WAIT(1);
        } else {
            CP_WAIT(0);
        }
        __syncthreads();

        const uint32_t st = sb + cur * STAGE_B;
#pragma unroll
        for (int s = 0; s < 2; ++s) {      // two k16 steps
            const uint32_t ks = s * 32;    // 16 bf16 = 32 bytes
            uint32_t ah[2][4], al[2][4];
#pragma unroll
            for (int i = 0; i < 2; ++i) {
                uint32_t off = (mbase + i * 16 + a_row) * RSTRIDE + ks + a_kh;
                ldmx4(ah[i], st + 0 * TILE_B + off);
                ldmx4(al[i], st + 1 * TILE_B + off);
            }
            uint32_t bh[8][2], bl[8][2];
#pragma unroll
            for (int jp = 0; jp < 4; ++jp) {
                uint32_t off = (nbase + jp * 16 + b_row) * RSTRIDE + ks + b_kh;
                uint32_t th[4], tl[4];
                ldmx4(th, st + 2 * TILE_B + off);
                ldmx4(tl, st + 3 * TILE_B + off);
                bh[jp * 2][0] = th[0]; bh[jp * 2][1] = th[1];
                bh[jp * 2 + 1][0] = th[2]; bh[jp * 2 + 1][1] = th[3];
                bl[jp * 2][0] = tl[0]; bl[jp * 2][1] = tl[1];
                bl[jp * 2 + 1][0] = tl[2]; bl[jp * 2 + 1][1] = tl[3];
            }
#pragma unroll
            for (int i = 0; i < 2; ++i)
#pragma unroll
                for (int j = 0; j < 8; ++j) {
                    mma_bf16(acc[i][j], ah[i], bh[j]);   // hi*hi
                    mma_bf16(acc[i][j], ah[i], bl[j]);   // hi*lo
                    mma_bf16(acc[i][j], al[i], bh[j]);   // lo*hi
                }
        }
        __syncthreads();
    }

    // epilogue: + bias
#pragma unroll
    for (int i = 0; i < 2; ++i) {
        const int r0 = rowBase + mbase + i * 16 + (lane >> 2);
#pragma unroll
        for (int j = 0; j < 8; ++j) {
            const int col = colBase + nbase + j * 8 + (lane & 3) * 2;
            const float b0 = bias[col], b1 = bias[col + 1];
            float2 v0 = make_float2(acc[i][j][0] + b0, acc[i][j][1] + b1);
            float2 v1 = make_float2(acc[i][j][2] + b0, acc[i][j][3] + b1);
            *(float2*)(C + (size_t)r0 * DM_ + col)       = v0;
            *(float2*)(C + (size_t)(r0 + 8) * DM_ + col) = v1;
        }
    }
}

// ===========================================================================
// Flash attention, fp32 (unchanged from R1).
// ===========================================================================
#define FSP 68

__global__ __launch_bounds__(256, 2)
void flash_attn(const float* __restrict__ Qg, const float* __restrict__ Kg,
                const float* __restrict__ Vg, float* __restrict__ Og)
{
    extern __shared__ float sm[];
    float* QsT = sm;
    float* KsT = QsT + 64 * FSP;
    float* PsT = KsT + 64 * FSP;
    float* Vs  = PsT + 64 * FSP;
    float* rm  = Vs + 64 * 64;
    float* rl  = rm + 64;
    float* rc  = rl + 64;

    const int tid = threadIdx.x;
    const int bh  = blockIdx.y;
    const int b   = bh >> 4;
    const int h   = bh & 15;
    const int q0  = blockIdx.x * 64;

    const size_t rowStart = (size_t)b * S_;
    const int    colOff   = h * DH_;

#pragma unroll
    for (int it = 0; it < 4; ++it) {
        const int chunk = tid + it * 256;
        const int r  = chunk >> 4;
        const int d4 = (chunk & 15) << 2;
        float4 v = *(const float4*)(Qg + (rowStart + q0 + r) * DM_ + colOff + d4);
        QsT[(d4 + 0) * FSP + r] = v.x;
        QsT[(d4 + 1) * FSP + r] = v.y;
        QsT[(d4 + 2) * FSP + r] = v.z;
        QsT[(d4 + 3) * FSP + r] = v.w;
    }
    if (tid < 64) { rm[tid] = -INFINITY; rl[tid] = 0.f; }

    const int ty = tid >> 4;
    const int tx = tid & 15;

    float o[16];
#pragma unroll
    for (int i = 0; i < 16; ++i) o[i] = 0.f;

    for (int jt = 0; jt < S_ / 64; ++jt) {
        const int k0 = jt * 64;

#pragma unroll
        for (int it = 0; it < 4; ++it) {
            const int chunk = tid + it * 256;
            const int r  = chunk >> 4;
            const int d4 = (chunk & 15) << 2;
            float4 kv = *(const float4*)(Kg + (rowStart + k0 + r) * DM_ + colOff + d4);
            KsT[(d4 + 0) * FSP + r] = kv.x;
            KsT[(d4 + 1) * FSP + r] = kv.y;
            KsT[(d4 + 2) * FSP + r] = kv.z;
            KsT[(d4 + 3) * FSP + r] = kv.w;
            float4 vv = *(const float4*)(Vg + (rowStart + k0 + r) * DM_ + colOff + d4);
            *(float4*)&Vs[r * 64 + d4] = vv;
        }
        __syncthreads();

        float s[16];
#pragma unroll
        for (int i = 0; i < 16; ++i) s[i] = 0.f;
        {
            const float* qa = QsT + ty * 4;
            const float* kb = KsT + tx * 4;
#pragma unroll
            for (int d = 0; d < 64; ++d) {
                float4 a = *(const float4*)(qa + d * FSP);
                float4 c = *(const float4*)(kb + d * FSP);
                float af[4] = {a.x, a.y, a.z, a.w};
                float cf[4] = {c.x, c.y, c.z, c.w};
#pragma unroll
                for (int i = 0; i < 4; ++i)
#pragma unroll
                    for (int j = 0; j < 4; ++j)
                        s[i * 4 + j] = fmaf(af[i], cf[j], s[i * 4 + j]);
            }
        }
#pragma unroll
        for (int j = 0; j < 4; ++j) {
            float4 w;
            w.x = s[0 * 4 + j] * 0.125f;
            w.y = s[1 * 4 + j] * 0.125f;
            w.z = s[2 * 4 + j] * 0.125f;
            w.w = s[3 * 4 + j] * 0.125f;
            *(float4*)&PsT[(tx * 4 + j) * FSP + ty * 4] = w;
        }
        __syncthreads();

        {
            const int r    = tid >> 2;
            const int part = tid & 3;
            float* prow = PsT + r;
            float mloc = -INFINITY;
#pragma unroll
            for (int k = 0; k < 16; ++k)
                mloc = fmaxf(mloc, prow[(part * 16 + k) * FSP]);
            mloc = fmaxf(mloc, __shfl_xor_sync(0xffffffffu, mloc, 1));
            mloc = fmaxf(mloc, __shfl_xor_sync(0xffffffffu, mloc, 2));
            const float mold = rm[r];
            const float mnew = fmaxf(mold, mloc);
            float sum = 0.f;
#pragma unroll
            for (int k = 0; k < 16; ++k) {
                const int kk = part * 16 + k;
                float p = __expf(prow[kk * FSP] - mnew);
                prow[kk * FSP] = p;
                sum += p;
            }
            sum += __shfl_xor_sync(0xffffffffu, sum, 1);
            sum += __shfl_xor_sync(0xffffffffu, sum, 2);
            if (part == 0) {
                const float cc = __expf(mold - mnew);
                rc[r] = cc;
                rm[r] = mnew;
                rl[r] = rl[r] * cc + sum;
            }
        }
        __syncthreads();

        {
            float cf[4];
#pragma unroll
            for (int i = 0; i < 4; ++i) cf[i] = rc[ty * 4 + i];
#pragma unroll
            for (int i = 0; i < 4; ++i)
#pragma unroll
                for (int j = 0; j < 4; ++j) o[i * 4 + j] *= cf[i];

            const float* pa = PsT + ty * 4;
            const float* vb = Vs + tx * 4;
#pragma unroll
            for (int k = 0; k < 64; ++k) {
                float4 a = *(const float4*)(pa + k * FSP);
                float4 v = *(const float4*)(vb + k * 64);
                float af[4] = {a.x, a.y, a.z, a.w};
                float vf[4] = {v.x, v.y, v.z, v.w};
#pragma unroll
                for (int i = 0; i < 4; ++i)
#pragma unroll
                    for (int j = 0; j < 4; ++j)
                        o[i * 4 + j] = fmaf(af[i], vf[j], o[i * 4 + j]);
            }
        }
        __syncthreads();
    }

    float inv[4];
#pragma unroll
    for (int i = 0; i < 4; ++i) inv[i] = 1.f / rl[ty * 4 + i];
#pragma unroll
    for (int i = 0; i < 4; ++i) {
        float4 w;
        w.x = o[i * 4 + 0] * inv[i];
        w.y = o[i * 4 + 1] * inv[i];
        w.z = o[i * 4 + 2] * inv[i];
        w.w = o[i * 4 + 3] * inv[i];
        *(float4*)(Og + (rowStart + q0 + ty * 4 + i) * DM_ + colOff + tx * 4) = w;
    }
}

// ===========================================================================
// Launch
// ===========================================================================
extern "C" void kernel_launch(void* const* d_in, const int* in_sizes, int n_in,
                              void* d_out, int out_size)
{
    const float* query = (const float*)d_in[0];
    const float* key   = (const float*)d_in[1];
    const float* value = (const float*)d_in[2];
    const float* Wq    = (const float*)d_in[3];
    const float* bq    = (const float*)d_in[4];
    const float* Wk    = (const float*)d_in[5];
    const float* bk    = (const float*)d_in[6];
    const float* Wv    = (const float*)d_in[7];
    const float* bv    = (const float*)d_in[8];
    const float* Wo    = (const float*)d_in[9];
    const float* bo    = (const float*)d_in[10];
    float* out = (float*)d_out;

    float *pQ, *pK, *pV, *pAO;
    __nv_bfloat16 *pAhi, *pAlo, *pWhi, *pWlo;
    cudaGetSymbolAddress((void**)&pQ,   g_Q);
    cudaGetSymbolAddress((void**)&pK,   g_K);
    cudaGetSymbolAddress((void**)&pV,   g_V);
    cudaGetSymbolAddress((void**)&pAO,  g_AO);
    cudaGetSymbolAddress((void**)&pAhi, g_Ahi);
    cudaGetSymbolAddress((void**)&pAlo, g_Alo);
    cudaGetSymbolAddress((void**)&pWhi, g_Whi);
    cudaGetSymbolAddress((void**)&pWlo, g_Wlo);

    static bool attrs_set = false;
    if (!attrs_set) {
        cudaFuncSetAttribute(gemm_mma, cudaFuncAttributeMaxDynamicSharedMemorySize, GEMM_SMEM);
        const int smemFA = (3 * 64 * FSP + 64 * 64 + 3 * 64) * (int)sizeof(float);
        cudaFuncSetAttribute(flash_attn, cudaFuncAttributeMaxDynamicSharedMemorySize, smemFA);
        attrs_set = true;
    }

    const int n4 = ROWS_ * DM_ / 4;
    const dim3 spGrid((n4 + 255) / 256), spBlk(256);
    const dim3 wtGrid(32, 32), wtBlk(32, 8);
    const dim3 gmGrid(DM_ / BN, ROWS_ / BM);   // (8, 64)
    const dim3 gmBlk(256);

    // ---- projections on tensor cores (bf16 hi/lo split) ----
    split_bf16<<<spGrid, spBlk>>>((const float4*)query, pAhi, pAlo, n4);
    wtsplit<<<wtGrid, wtBlk>>>(Wq, pWhi, pWlo);
    gemm_mma<<<gmGrid, gmBlk, GEMM_SMEM>>>(pAhi, pAlo, pWhi, pWlo, bq, pQ);

    split_bf16<<<spGrid, spBlk>>>((const float4*)key, pAhi, pAlo, n4);
    wtsplit<<<wtGrid, wtBlk>>>(Wk, pWhi, pWlo);
    gemm_mma<<<gmGrid, gmBlk, GEMM_SMEM>>>(pAhi, pAlo, pWhi, pWlo, bk, pK);

    split_bf16<<<spGrid, spBlk>>>((const float4*)value, pAhi, pAlo, n4);
    wtsplit<<<wtGrid, wtBlk>>>(Wv, pWhi, pWlo);
    gemm_mma<<<gmGrid, gmBlk, GEMM_SMEM>>>(pAhi, pAlo, pWhi, pWlo, bv, pV);

    // ---- attention (fp32, unchanged) ----
    const int smemFA = (3 * 64 * FSP + 64 * 64 + 3 * 64) * (int)sizeof(float);
    dim3 aGrid(S_ / 64, B_ * NH_);
    flash_attn<<<aGrid, dim3(256), smemFA>>>(pQ, pK, pV, pAO);

    // ---- output projection ----
    split_bf16<<<spGrid, spBlk>>>((const float4*)pAO, pAhi, pAlo, n4);
    wtsplit<<<wtGrid, wtBlk>>>(Wo, pWhi, pWlo);
    gemm_mma<<<gmGrid, gmBlk, GEMM_SMEM>>>(pAhi, pAlo, pWhi, pWlo, bo, out);
}

// round 4
// speedup vs baseline: 2.9065x; 2.1728x over previous
#include <cuda_runtime.h>
#include <cuda_bf16.h>
#include <math.h>
#include <cstdint>

// ---------------------------------------------------------------------------
// Problem constants
// ---------------------------------------------------------------------------
#define B_    4
#define S_    2048
#define DM_   1024
#define NH_   16
#define DH_   64
#define ROWS_ (B_ * S_)          // 8192

// ---------------------------------------------------------------------------
// Scratch (device globals: allocation-free per harness rules)
// ---------------------------------------------------------------------------
__device__ float g_AO[ROWS_ * DM_];
__device__ __nv_bfloat16 g_Ahi[ROWS_ * DM_];
__device__ __nv_bfloat16 g_Alo[ROWS_ * DM_];
__device__ __nv_bfloat16 g_Whi[DM_ * DM_];   // transposed: [N][K]
__device__ __nv_bfloat16 g_Wlo[DM_ * DM_];   // transposed: [N][K]
__device__ __nv_bfloat16 g_Qhi[ROWS_ * DM_];
__device__ __nv_bfloat16 g_Qlo[ROWS_ * DM_];
__device__ __nv_bfloat16 g_Khi[ROWS_ * DM_];
__device__ __nv_bfloat16 g_Klo[ROWS_ * DM_];
__device__ __nv_bfloat16 g_Vhi[ROWS_ * DM_];
__device__ __nv_bfloat16 g_Vlo[ROWS_ * DM_];

// ===========================================================================
// Generic-PTX helpers (legal on plain sm_103 target: sm_80+ instructions)
// ===========================================================================
__device__ __forceinline__ uint32_t smem_u32(const void* p) {
    uint32_t a;
    asm("{ .reg .u64 t; cvta.to.shared.u64 t, %1; cvt.u32.u64 %0, t; }"
        : "=r"(a) : "l"(p));
    return a;
}

__device__ __forceinline__ void cp16(uint32_t s, const void* g) {
    asm volatile("cp.async.cg.shared.global [%0], [%1], 16;" :: "r"(s), "l"(g));
}
#define CP_COMMIT() asm volatile("cp.async.commit_group;" ::: "memory")
#define CP_WAIT(n)  asm volatile("cp.async.wait_group %0;" :: "n"(n) : "memory")

__device__ __forceinline__ void ldmx4(uint32_t* r, uint32_t addr) {
    asm volatile("ldmatrix.sync.aligned.m8n8.x4.shared.b16 {%0,%1,%2,%3}, [%4];"
                 : "=r"(r[0]), "=r"(r[1]), "=r"(r[2]), "=r"(r[3]) : "r"(addr));
}

__device__ __forceinline__ void ldmx4t(uint32_t* r, uint32_t addr) {
    asm volatile("ldmatrix.sync.aligned.m8n8.x4.trans.shared.b16 {%0,%1,%2,%3}, [%4];"
                 : "=r"(r[0]), "=r"(r[1]), "=r"(r[2]), "=r"(r[3]) : "r"(addr));
}

__device__ __forceinline__ void mma_bf16(float* d, const uint32_t* a,
                                         const uint32_t* b) {
    asm volatile(
        "mma.sync.aligned.m16n8k16.row.col.f32.bf16.bf16.f32 "
        "{%0,%1,%2,%3}, {%4,%5,%6,%7}, {%8,%9}, {%0,%1,%2,%3};"
        : "+f"(d[0]), "+f"(d[1]), "+f"(d[2]), "+f"(d[3])
        : "r"(a[0]), "r"(a[1]), "r"(a[2]), "r"(a[3]), "r"(b[0]), "r"(b[1]));
}

// pack two fp32 into bf16x2: hi_elem -> upper 16 bits, lo_elem -> lower
__device__ __forceinline__ uint32_t cvt_bf16x2(float hi_elem, float lo_elem) {
    uint32_t r;
    asm("cvt.rn.satfinite.bf16x2.f32 %0, %1, %2;"
        : "=r"(r) : "f"(hi_elem), "f"(lo_elem));
    return r;
}

__device__ __forceinline__ float ex2f(float x) {
    float y;
    asm("ex2.approx.ftz.f32 %0, %1;" : "=f"(y) : "f"(x));
    return y;
}

// ===========================================================================
// Prep kernels: fp32 -> bf16 hi/lo split; W transpose+split
// ===========================================================================
__global__ __launch_bounds__(256)
void split_bf16(const float4* __restrict__ x, __nv_bfloat16* __restrict__ hi,
                __nv_bfloat16* __restrict__ lo, int n4) {
    int i = blockIdx.x * blockDim.x + threadIdx.x;
    if (i >= n4) return;
    float4 v = x[i];
    float f[4] = {v.x, v.y, v.z, v.w};
    __nv_bfloat16 h[4], l[4];
#pragma unroll
    for (int j = 0; j < 4; ++j) {
        h[j] = __float2bfloat16_rn(f[j]);
        l[j] = __float2bfloat16_rn(f[j] - __bfloat162float(h[j]));
    }
    ((__nv_bfloat162*)hi)[i * 2 + 0] = __nv_bfloat162(h[0], h[1]);
    ((__nv_bfloat162*)hi)[i * 2 + 1] = __nv_bfloat162(h[2], h[3]);
    ((__nv_bfloat162*)lo)[i * 2 + 0] = __nv_bfloat162(l[0], l[1]);
    ((__nv_bfloat162*)lo)[i * 2 + 1] = __nv_bfloat162(l[2], l[3]);
}

// W[K][N] fp32 -> Wt hi/lo [N][K] bf16 (tiled transpose)
__global__ __launch_bounds__(256)
void wtsplit(const float* __restrict__ W, __nv_bfloat16* __restrict__ hi,
             __nv_bfloat16* __restrict__ lo) {
    __shared__ float t[32][33];
    const int n0 = blockIdx.x * 32;
    const int k0 = blockIdx.y * 32;
    const int tx = threadIdx.x, ty = threadIdx.y;
#pragma unroll
    for (int i = 0; i < 4; ++i)
        t[ty + i * 8][tx] = W[(size_t)(k0 + ty + i * 8) * DM_ + n0 + tx];
    __syncthreads();
#pragma unroll
    for (int i = 0; i < 4; ++i) {
        float v = t[tx][ty + i * 8];
        __nv_bfloat16 h = __float2bfloat16_rn(v);
        __nv_bfloat16 l = __float2bfloat16_rn(v - __bfloat162float(h));
        size_t o = (size_t)(n0 + ty + i * 8) * DM_ + k0 + tx;
        hi[o] = h;
        lo[o] = l;
    }
}

// ===========================================================================
// HMMA GEMM (bf16 hi/lo split x3):  C = A @ Wt^T + bias
//   Epilogue: fp32 C (if C != null) OR bf16 hi/lo pair (Chi/Clo).
// ===========================================================================
#define BM 128
#define BN 128
#define BK 32
#define NKT (DM_ / BK)            // 32
#define RSTRIDE 80                // bytes per 32-bf16 row in smem
#define TILE_B (128 * RSTRIDE)    // 10240 B
#define STAGE_B (4 * TILE_B)      // Ahi,Alo,Bhi,Blo
#define GEMM_SMEM (2 * STAGE_B)   // 81920 B

__device__ __forceinline__ void load_ktile(uint32_t sb, int kt, int stage,
                                           const __nv_bfloat16* Ahi,
                                           const __nv_bfloat16* Alo,
                                           const __nv_bfloat16* Bhi,
                                           const __nv_bfloat16* Blo,
                                           int rowBase, int colBase) {
    const int tid = threadIdx.x;
    const uint32_t base = sb + stage * STAGE_B;
    const __nv_bfloat16* srcs[4] = {
        Ahi + (size_t)rowBase * DM_ + kt * BK,
        Alo + (size_t)rowBase * DM_ + kt * BK,
        Bhi + (size_t)colBase * DM_ + kt * BK,
        Blo + (size_t)colBase * DM_ + kt * BK};
#pragma unroll
    for (int t = 0; t < 4; ++t) {
#pragma unroll
        for (int i = 0; i < 2; ++i) {
            int c = tid + i * 256;          // 0..511 chunks (128 rows x 4)
            int r = c >> 2, ch = c & 3;
            cp16(base + t * TILE_B + r * RSTRIDE + ch * 16,
                 srcs[t] + (size_t)r * DM_ + ch * 8);
        }
    }
}

__global__ __launch_bounds__(256)
void gemm_mma(const __nv_bfloat16* __restrict__ Ahi,
              const __nv_bfloat16* __restrict__ Alo,
              const __nv_bfloat16* __restrict__ Bhi,
              const __nv_bfloat16* __restrict__ Blo,
              const float* __restrict__ bias, float* __restrict__ C,
              __nv_bfloat16* __restrict__ Chi, __nv_bfloat16* __restrict__ Clo) {
    extern __shared__ char smem[];
    const uint32_t sb = smem_u32(smem);
    const int tid  = threadIdx.x;
    const int wid  = tid >> 5;
    const int lane = tid & 31;
    const int rowBase = blockIdx.y * BM;
    const int colBase = blockIdx.x * BN;

    const int mbase = (wid >> 1) * 32;   // 4 warps along M
    const int nbase = (wid & 1) * 64;    // 2 warps along N

    float acc[2][8][4];
#pragma unroll
    for (int i = 0; i < 2; ++i)
#pragma unroll
        for (int j = 0; j < 8; ++j)
#pragma unroll
            for (int q = 0; q < 4; ++q) acc[i][j][q] = 0.f;

    load_ktile(sb, 0, 0, Ahi, Alo, Bhi, Blo, rowBase, colBase);
    CP_COMMIT();

    const int a_row = lane & 15;
    const int a_kh  = (lane >> 4) << 4;
    const int b_row = ((lane >> 4) & 1) * 8 + (lane & 7);
    const int b_kh  = ((lane >> 3) & 1) << 4;

    for (int kt = 0; kt < NKT; ++kt) {
        const int cur = kt & 1;
        if (kt + 1 < NKT) {
            load_ktile(sb, kt + 1, cur ^ 1, Ahi, Alo, Bhi, Blo, rowBase, colBase);
            CP_COMMIT();
            CP_WAIT(1);
        } else {
            CP_WAIT(0);
        }
        __syncthreads();

        const uint32_t st = sb + cur * STAGE_B;
#pragma unroll
        for (int s = 0; s < 2; ++s) {
            const uint32_t ks = s * 32;
            uint32_t ah[2][4], al[2][4];
#pragma unroll
            for (int i = 0; i < 2; ++i) {
                uint32_t off = (mbase + i * 16 + a_row) * RSTRIDE + ks + a_kh;
                ldmx4(ah[i], st + 0 * TILE_B + off);
                ldmx4(al[i], st + 1 * TILE_B + off);
            }
            uint32_t bh[8][2], bl[8][2];
#pragma unroll
            for (int jp = 0; jp < 4; ++jp) {
                uint32_t off = (nbase + jp * 16 + b_row) * RSTRIDE + ks + b_kh;
                uint32_t th[4], tl[4];
                ldmx4(th, st + 2 * TILE_B + off);
                ldmx4(tl, st + 3 * TILE_B + off);
                bh[jp * 2][0] = th[0]; bh[jp * 2][1] = th[1];
                bh[jp * 2 + 1][0] = th[2]; bh[jp * 2 + 1][1] = th[3];
                bl[jp * 2][0] = tl[0]; bl[jp * 2][1] = tl[1];
                bl[jp * 2 + 1][0] = tl[2]; bl[jp * 2 + 1][1] = tl[3];
            }
#pragma unroll
            for (int i = 0; i < 2; ++i)
#pragma unroll
                for (int j = 0; j < 8; ++j) {
                    mma_bf16(acc[i][j], ah[i], bh[j]);
                    mma_bf16(acc[i][j], ah[i], bl[j]);
                    mma_bf16(acc[i][j], al[i], bh[j]);
                }
        }
        __syncthreads();
    }

    // epilogue
#pragma unroll
    for (int i = 0; i < 2; ++i) {
        const int r0 = rowBase + mbase + i * 16 + (lane >> 2);
#pragma unroll
        for (int j = 0; j < 8; ++j) {
            const int col = colBase + nbase + j * 8 + (lane & 3) * 2;
            const float b0 = bias[col], b1 = bias[col + 1];
            float f0 = acc[i][j][0] + b0, f1 = acc[i][j][1] + b1;
            float f2 = acc[i][j][2] + b0, f3 = acc[i][j][3] + b1;
            if (C) {
                *(float2*)(C + (size_t)r0 * DM_ + col)       = make_float2(f0, f1);
                *(float2*)(C + (size_t)(r0 + 8) * DM_ + col) = make_float2(f2, f3);
            } else {
                uint32_t h01 = cvt_bf16x2(f1, f0);
                uint32_t h23 = cvt_bf16x2(f3, f2);
                float r0f = f0 - __uint_as_float(h01 << 16);
                float r1f = f1 - __uint_as_float(h01 & 0xFFFF0000u);
                float r2f = f2 - __uint_as_float(h23 << 16);
                float r3f = f3 - __uint_as_float(h23 & 0xFFFF0000u);
                uint32_t l01 = cvt_bf16x2(r1f, r0f);
                uint32_t l23 = cvt_bf16x2(r3f, r2f);
                *(uint32_t*)(Chi + (size_t)r0 * DM_ + col)       = h01;
                *(uint32_t*)(Chi + (size_t)(r0 + 8) * DM_ + col) = h23;
                *(uint32_t*)(Clo + (size_t)r0 * DM_ + col)       = l01;
                *(uint32_t*)(Clo + (size_t)(r0 + 8) * DM_ + col) = l23;
            }
        }
    }
}

// ===========================================================================
// Flash attention on mma.sync (bf16 hi/lo x3 for QK^T and PV).
// CTA: 64 q-rows x Dh=64, loop over 32 kv tiles of 64. 256 threads (8 warps:
// 4 along M x 2 along KV/d). Smem tiles padded to 72 bf16 (144B) rows.
// ===========================================================================
#define ATS   72
#define ATSB  144
#define TTS   (64 * ATSB)        // 9216 B per 64x64 bf16 tile
#define KVBASE (2 * TTS)         // Qhi,Qlo first
#define STG    (4 * TTS)         // Khi,Klo,Vhi,Vlo per stage
#define FA_STATS (KVBASE + 2 * STG)   // 92160
#define FA_SMEM  (FA_STATS + 1024)    // 93184

#define C2F 0.1803368801111204f  // log2(e) / 8  (Dh=64 scale folded into exp2)

__device__ __forceinline__ void fa_load_kv(uint32_t sb, int stage, int k0,
    const __nv_bfloat16* Khi, const __nv_bfloat16* Klo,
    const __nv_bfloat16* Vhi, const __nv_bfloat16* Vlo,
    size_t rowStart, int colOff) {
    const int tid = threadIdx.x;
    const __nv_bfloat16* srcs[4] = {
        Khi + (rowStart + k0) * DM_ + colOff,
        Klo + (rowStart + k0) * DM_ + colOff,
        Vhi + (rowStart + k0) * DM_ + colOff,
        Vlo + (rowStart + k0) * DM_ + colOff};
    const uint32_t base = sb + KVBASE + stage * STG;
#pragma unroll
    for (int t = 0; t < 4; ++t) {
#pragma unroll
        for (int i = 0; i < 2; ++i) {
            int c = tid + i * 256;       // 0..511: r = c>>3 (64 rows), ch = c&7
            int r = c >> 3, ch = c & 7;
            cp16(base + t * TTS + r * ATSB + ch * 16,
                 srcs[t] + (size_t)r * DM_ + ch * 8);
        }
    }
}

__global__ __launch_bounds__(256, 2)
void flash_mma(const __nv_bfloat16* __restrict__ Qhi,
               const __nv_bfloat16* __restrict__ Qlo,
               const __nv_bfloat16* __restrict__ Khi,
               const __nv_bfloat16* __restrict__ Klo,
               const __nv_bfloat16* __restrict__ Vhi,
               const __nv_bfloat16* __restrict__ Vlo,
               float* __restrict__ AO) {
    extern __shared__ char smem[];
    const uint32_t sb = smem_u32(smem);
    const int tid = threadIdx.x, wid = tid >> 5, lane = tid & 31;
    const int wm = wid >> 1, wn = wid & 1;
    const int bh = blockIdx.y, b = bh >> 4, h = bh & 15;
    const int q0 = blockIdx.x * 64;
    const size_t rowStart = (size_t)b * S_;
    const int colOff = h * DH_;

    float* sPM = (float*)(smem + FA_STATS);   // [2][64]
    float* sPS = sPM + 128;                   // [2][64]

    // ---- Q loads (hi & lo) ----
    {
        const __nv_bfloat16* qs[2] = {Qhi + (rowStart + q0) * DM_ + colOff,
                                      Qlo + (rowStart + q0) * DM_ + colOff};
#pragma unroll
        for (int t = 0; t < 2; ++t)
#pragma unroll
            for (int i = 0; i < 2; ++i) {
                int c = tid + i * 256;
                int r = c >> 3, ch = c & 7;
                cp16(sb + t * TTS + r * ATSB + ch * 16,
                     qs[t] + (size_t)r * DM_ + ch * 8);
            }
    }
    fa_load_kv(sb, 0, 0, Khi, Klo, Vhi, Vlo, rowStart, colOff);
    CP_COMMIT();

    // fragment addressing
    const int a_row = lane & 15;
    const int a_kh  = (lane >> 4) << 4;
    const int b_row = ((lane >> 4) & 1) * 8 + (lane & 7);
    const int b_kh  = ((lane >> 3) & 1) << 4;
    const int v_k   = (lane & 7) + ((lane >> 3) & 1) * 8;
    const int v_d8  = ((lane >> 4) & 1) * 8;
    const int r     = lane >> 2;             // row within 16
    const int rowA  = 16 * wm + r;           // row within 64

    float m0 = -1e30f, m1 = -1e30f, l0 = 0.f, l1 = 0.f;
    float o[8][4];
#pragma unroll
    for (int j = 0; j < 8; ++j)
#pragma unroll
        for (int q = 0; q < 4; ++q) o[j][q] = 0.f;

    const uint32_t qaddr = sb + (16 * wm + a_row) * ATSB + a_kh;

    for (int jt = 0; jt < S_ / 64; ++jt) {
        CP_WAIT(0);
        __syncthreads();
        const uint32_t kvb = sb + KVBASE + (jt & 1) * STG;
        if (jt + 1 < S_ / 64) {
            fa_load_kv(sb, (jt + 1) & 1, (jt + 1) * 64, Khi, Klo, Vhi, Vlo,
                       rowStart, colOff);
            CP_COMMIT();
        }

        // ---- scores: S = Q K^T (raw, x3 hi/lo passes) ----
        float s[4][4];
#pragma unroll
        for (int j = 0; j < 4; ++j)
#pragma unroll
            for (int q = 0; q < 4; ++q) s[j][q] = 0.f;

#pragma unroll
        for (int ks = 0; ks < 4; ++ks) {
            uint32_t aqh[4], aql[4];
            ldmx4(aqh, qaddr + ks * 32);
            ldmx4(aql, qaddr + TTS + ks * 32);
            uint32_t kh[4][2], kl[4][2];
#pragma unroll
            for (int nt = 0; nt < 2; ++nt) {
                uint32_t addr = kvb + (32 * wn + nt * 16 + b_row) * ATSB +
                                ks * 32 + b_kh;
                uint32_t th[4], tl[4];
                ldmx4(th, addr);              // Khi (tile 0 of stage)
                ldmx4(tl, addr + TTS);        // Klo
                kh[nt * 2][0] = th[0]; kh[nt * 2][1] = th[1];
                kh[nt * 2 + 1][0] = th[2]; kh[nt * 2 + 1][1] = th[3];
                kl[nt * 2][0] = tl[0]; kl[nt * 2][1] = tl[1];
                kl[nt * 2 + 1][0] = tl[2]; kl[nt * 2 + 1][1] = tl[3];
            }
#pragma unroll
            for (int j = 0; j < 4; ++j) {
                mma_bf16(s[j], aqh, kh[j]);
                mma_bf16(s[j], aqh, kl[j]);
                mma_bf16(s[j], aql, kh[j]);
            }
        }

        // ---- online softmax ----
        float rmax0 = -1e30f, rmax1 = -1e30f;
#pragma unroll
        for (int j = 0; j < 4; ++j) {
            rmax0 = fmaxf(rmax0, fmaxf(s[j][0], s[j][1]));
            rmax1 = fmaxf(rmax1, fmaxf(s[j][2], s[j][3]));
        }
        rmax0 = fmaxf(rmax0, __shfl_xor_sync(0xffffffffu, rmax0, 1));
        rmax0 = fmaxf(rmax0, __shfl_xor_sync(0xffffffffu, rmax0, 2));
        rmax1 = fmaxf(rmax1, __shfl_xor_sync(0xffffffffu, rmax1, 1));
        rmax1 = fmaxf(rmax1, __shfl_xor_sync(0xffffffffu, rmax1, 2));
        if ((lane & 3) == 0) {
            sPM[wn * 64 + rowA]     = rmax0;
            sPM[wn * 64 + rowA + 8] = rmax1;
        }
        __syncthreads();
        const float m0n = fmaxf(m0, fmaxf(sPM[rowA], sPM[64 + rowA]));
        const float m1n = fmaxf(m1, fmaxf(sPM[rowA + 8], sPM[64 + rowA + 8]));
        const float c0 = ex2f((m0 - m0n) * C2F);
        const float c1 = ex2f((m1 - m1n) * C2F);
        m0 = m0n; m1 = m1n;
#pragma unroll
        for (int j = 0; j < 8; ++j) {
            o[j][0] *= c0; o[j][1] *= c0;
            o[j][2] *= c1; o[j][3] *= c1;
        }
        float p[4][4];
        float sum0 = 0.f, sum1 = 0.f;
#pragma unroll
        for (int j = 0; j < 4; ++j) {
            p[j][0] = ex2f((s[j][0] - m0) * C2F);
            p[j][1] = ex2f((s[j][1] - m0) * C2F);
            p[j][2] = ex2f((s[j][2] - m1) * C2F);
            p[j][3] = ex2f((s[j][3] - m1) * C2F);
            sum0 += p[j][0] + p[j][1];
            sum1 += p[j][2] + p[j][3];
        }
        sum0 += __shfl_xor_sync(0xffffffffu, sum0, 1);
        sum0 += __shfl_xor_sync(0xffffffffu, sum0, 2);
        sum1 += __shfl_xor_sync(0xffffffffu, sum1, 1);
        sum1 += __shfl_xor_sync(0xffffffffu, sum1, 2);
        if ((lane & 3) == 0) {
            sPS[wn * 64 + rowA]     = sum0;
            sPS[wn * 64 + rowA + 8] = sum1;
        }
        __syncthreads();
        l0 = l0 * c0 + sPS[rowA]     + sPS[64 + rowA];
        l1 = l1 * c1 + sPS[rowA + 8] + sPS[64 + rowA + 8];

        // ---- pack P into bf16 hi/lo A-fragments (in registers) ----
        uint32_t PAh[4], PBh[4], PAl[4], PBl[4];
#pragma unroll
        for (int j = 0; j < 4; ++j) {
            PAh[j] = cvt_bf16x2(p[j][1], p[j][0]);
            PBh[j] = cvt_bf16x2(p[j][3], p[j][2]);
            float ra0 = p[j][0] - __uint_as_float(PAh[j] << 16);
            float ra1 = p[j][1] - __uint_as_float(PAh[j] & 0xFFFF0000u);
            float rb0 = p[j][2] - __uint_as_float(PBh[j] << 16);
            float rb1 = p[j][3] - __uint_as_float(PBh[j] & 0xFFFF0000u);
            PAl[j] = cvt_bf16x2(ra1, ra0);
            PBl[j] = cvt_bf16x2(rb1, rb0);
        }

        // ---- O += P @ V  (x3 hi/lo passes, V^T frags via ldmatrix.trans) ----
#pragma unroll
        for (int s2 = 0; s2 < 2; ++s2) {
            uint32_t ah[4] = {PAh[2 * s2], PBh[2 * s2], PAh[2 * s2 + 1], PBh[2 * s2 + 1]};
            uint32_t al[4] = {PAl[2 * s2], PBl[2 * s2], PAl[2 * s2 + 1], PBl[2 * s2 + 1]};
#pragma unroll
            for (int dt = 0; dt < 4; ++dt) {
                uint32_t addr = kvb + 2 * TTS + (32 * wn + 16 * s2 + v_k) * ATSB +
                                (dt * 16 + v_d8) * 2;
                uint32_t vh[4], vl[4];
                ldmx4t(vh, addr);             // Vhi
                ldmx4t(vl, addr + TTS);       // Vlo
                uint32_t bh0[2] = {vh[0], vh[1]}, bh1[2] = {vh[2], vh[3]};
                uint32_t bl0[2] = {vl[0], vl[1]}, bl1[2] = {vl[2], vl[3]};
                mma_bf16(o[2 * dt], ah, bh0);
                mma_bf16(o[2 * dt], ah, bl0);
                mma_bf16(o[2 * dt], al, bh0);
                mma_bf16(o[2 * dt + 1], ah, bh1);
                mma_bf16(o[2 * dt + 1], ah, bl1);
                mma_bf16(o[2 * dt + 1], al, bh1);
            }
        }
    }

    // ---- merge wn halves (smem aliased over dead K/V buffers), write out ----
    __syncthreads();
    float* Om = (float*)(smem + KVBASE);      // 64 x 64 fp32
    if (wn == 1) {
#pragma unroll
        for (int j = 0; j < 8; ++j) {
            const int col = j * 8 + (lane & 3) * 2;
            *(float2*)&Om[rowA * 64 + col]       = make_float2(o[j][0], o[j][1]);
            *(float2*)&Om[(rowA + 8) * 64 + col] = make_float2(o[j][2], o[j][3]);
        }
    }
    __syncthreads();
    if (wn == 0) {
        const float i0 = 1.f / l0, i1 = 1.f / l1;
        float* out0 = AO + (rowStart + q0 + rowA) * DM_ + colOff;
        float* out1 = AO + (rowStart + q0 + rowA + 8) * DM_ + colOff;
#pragma unroll
        for (int j = 0; j < 8; ++j) {
            const int col = j * 8 + (lane & 3) * 2;
            float2 a0 = *(float2*)&Om[rowA * 64 + col];
            float2 a1 = *(float2*)&Om[(rowA + 8) * 64 + col];
            *(float2*)(out0 + col) =
                make_float2((o[j][0] + a0.x) * i0, (o[j][1] + a0.y) * i0);
            *(float2*)(out1 + col) =
                make_float2((o[j][2] + a1.x) * i1, (o[j][3] + a1.y) * i1);
        }
    }
}

// ===========================================================================
// Launch
// ===========================================================================
extern "C" void kernel_launch(void* const* d_in, const int* in_sizes, int n_in,
                              void* d_out, int out_size)
{
    const float* query = (const float*)d_in[0];
    const float* key   = (const float*)d_in[1];
    const float* value = (const float*)d_in[2];
    const float* Wq    = (const float*)d_in[3];
    const float* bq    = (const float*)d_in[4];
    const float* Wk    = (const float*)d_in[5];
    const float* bk    = (const float*)d_in[6];
    const float* Wv    = (const float*)d_in[7];
    const float* bv    = (const float*)d_in[8];
    const float* Wo    = (const float*)d_in[9];
    const float* bo    = (const float*)d_in[10];
    float* out = (float*)d_out;

    float* pAO;
    __nv_bfloat16 *pAhi, *pAlo, *pWhi, *pWlo;
    __nv_bfloat16 *pQhi, *pQlo, *pKhi, *pKlo, *pVhi, *pVlo;
    cudaGetSymbolAddress((void**)&pAO,  g_AO);
    cudaGetSymbolAddress((void**)&pAhi, g_Ahi);
    cudaGetSymbolAddress((void**)&pAlo, g_Alo);
    cudaGetSymbolAddress((void**)&pWhi, g_Whi);
    cudaGetSymbolAddress((void**)&pWlo, g_Wlo);
    cudaGetSymbolAddress((void**)&pQhi, g_Qhi);
    cudaGetSymbolAddress((void**)&pQlo, g_Qlo);
    cudaGetSymbolAddress((void**)&pKhi, g_Khi);
    cudaGetSymbolAddress((void**)&pKlo, g_Klo);
    cudaGetSymbolAddress((void**)&pVhi, g_Vhi);
    cudaGetSymbolAddress((void**)&pVlo, g_Vlo);

    static bool attrs_set = false;
    if (!attrs_set) {
        cudaFuncSetAttribute(gemm_mma, cudaFuncAttributeMaxDynamicSharedMemorySize, GEMM_SMEM);
        cudaFuncSetAttribute(flash_mma, cudaFuncAttributeMaxDynamicSharedMemorySize, FA_SMEM);
        attrs_set = true;
    }

    const int n4 = ROWS_ * DM_ / 4;
    const dim3 spGrid((n4 + 255) / 256), spBlk(256);
    const dim3 wtGrid(32, 32), wtBlk(32, 8);
    const dim3 gmGrid(DM_ / BN, ROWS_ / BM);   // (8, 64)
    const dim3 gmBlk(256);

    // ---- projections (epilogue writes bf16 hi/lo directly) ----
    split_bf16<<<spGrid, spBlk>>>((const float4*)query, pAhi, pAlo, n4);
    wtsplit<<<wtGrid, wtBlk>>>(Wq, pWhi, pWlo);
    gemm_mma<<<gmGrid, gmBlk, GEMM_SMEM>>>(pAhi, pAlo, pWhi, pWlo, bq,
                                           nullptr, pQhi, pQlo);

    split_bf16<<<spGrid, spBlk>>>((const float4*)key, pAhi, pAlo, n4);
    wtsplit<<<wtGrid, wtBlk>>>(Wk, pWhi, pWlo);
    gemm_mma<<<gmGrid, gmBlk, GEMM_SMEM>>>(pAhi, pAlo, pWhi, pWlo, bk,
                                           nullptr, pKhi, pKlo);

    split_bf16<<<spGrid, spBlk>>>((const float4*)value, pAhi, pAlo, n4);
    wtsplit<<<wtGrid, wtBlk>>>(Wv, pWhi, pWlo);
    gemm_mma<<<gmGrid, gmBlk, GEMM_SMEM>>>(pAhi, pAlo, pWhi, pWlo, bv,
                                           nullptr, pVhi, pVlo);

    // ---- attention on tensor cores ----
    dim3 aGrid(S_ / 64, B_ * NH_);             // (32, 64)
    flash_mma<<<aGrid, dim3(256), FA_SMEM>>>(pQhi, pQlo, pKhi, pKlo,
                                             pVhi, pVlo, pAO);

    // ---- output projection (fp32 result) ----
    split_bf16<<<spGrid, spBlk>>>((const float4*)pAO, pAhi, pAlo, n4);
    wtsplit<<<wtGrid, wtBlk>>>(Wo, pWhi, pWlo);
    gemm_mma<<<gmGrid, gmBlk, GEMM_SMEM>>>(pAhi, pAlo, pWhi, pWlo, bo,
                                           out, nullptr, nullptr);
}

// round 5
// speedup vs baseline: 3.1135x; 1.0712x over previous
#include <cuda_runtime.h>
#include <cuda_bf16.h>
#include <math.h>
#include <cstdint>

// ---------------------------------------------------------------------------
// Problem constants
// ---------------------------------------------------------------------------
#define B_    4
#define S_    2048
#define DM_   1024
#define NH_   16
#define DH_   64
#define ROWS_ (B_ * S_)          // 8192

// ---------------------------------------------------------------------------
// Scratch (device globals: allocation-free per harness rules)
// ---------------------------------------------------------------------------
__device__ __nv_bfloat16 g_Ih[3][ROWS_ * DM_];   // split inputs (q,k,v) hi
__device__ __nv_bfloat16 g_Il[3][ROWS_ * DM_];   // split inputs lo
__device__ __nv_bfloat16 g_W4h[4][DM_ * DM_];    // W^T hi (q,k,v,o)
__device__ __nv_bfloat16 g_W4l[4][DM_ * DM_];    // W^T lo
__device__ __nv_bfloat16 g_Qh[ROWS_ * DM_];
__device__ __nv_bfloat16 g_Ql[ROWS_ * DM_];
__device__ __nv_bfloat16 g_Kh[ROWS_ * DM_];
__device__ __nv_bfloat16 g_Kl[ROWS_ * DM_];
__device__ __nv_bfloat16 g_Vh[ROWS_ * DM_];
__device__ __nv_bfloat16 g_Vl[ROWS_ * DM_];
__device__ __nv_bfloat16 g_AOh[ROWS_ * DM_];
__device__ __nv_bfloat16 g_AOl[ROWS_ * DM_];

// ===========================================================================
// Generic-PTX helpers (legal on plain sm_103 target: sm_80+ instructions)
// ===========================================================================
__device__ __forceinline__ uint32_t smem_u32(const void* p) {
    uint32_t a;
    asm("{ .reg .u64 t; cvta.to.shared.u64 t, %1; cvt.u32.u64 %0, t; }"
        : "=r"(a) : "l"(p));
    return a;
}

__device__ __forceinline__ void cp16(uint32_t s, const void* g) {
    asm volatile("cp.async.cg.shared.global [%0], [%1], 16;" :: "r"(s), "l"(g));
}
#define CP_COMMIT() asm volatile("cp.async.commit_group;" ::: "memory")
#define CP_WAIT(n)  asm volatile("cp.async.wait_group %0;" :: "n"(n) : "memory")

__device__ __forceinline__ void ldmx4(uint32_t* r, uint32_t addr) {
    asm volatile("ldmatrix.sync.aligned.m8n8.x4.shared.b16 {%0,%1,%2,%3}, [%4];"
                 : "=r"(r[0]), "=r"(r[1]), "=r"(r[2]), "=r"(r[3]) : "r"(addr));
}

__device__ __forceinline__ void ldmx4t(uint32_t* r, uint32_t addr) {
    asm volatile("ldmatrix.sync.aligned.m8n8.x4.trans.shared.b16 {%0,%1,%2,%3}, [%4];"
                 : "=r"(r[0]), "=r"(r[1]), "=r"(r[2]), "=r"(r[3]) : "r"(addr));
}

__device__ __forceinline__ void mma_bf16(float* d, const uint32_t* a,
                                         const uint32_t* b) {
    asm volatile(
        "mma.sync.aligned.m16n8k16.row.col.f32.bf16.bf16.f32 "
        "{%0,%1,%2,%3}, {%4,%5,%6,%7}, {%8,%9}, {%0,%1,%2,%3};"
        : "+f"(d[0]), "+f"(d[1]), "+f"(d[2]), "+f"(d[3])
        : "r"(a[0]), "r"(a[1]), "r"(a[2]), "r"(a[3]), "r"(b[0]), "r"(b[1]));
}

__device__ __forceinline__ uint32_t cvt_bf16x2(float hi_elem, float lo_elem) {
    uint32_t r;
    asm("cvt.rn.satfinite.bf16x2.f32 %0, %1, %2;"
        : "=r"(r) : "f"(hi_elem), "f"(lo_elem));
    return r;
}

__device__ __forceinline__ float ex2f(float x) {
    float y;
    asm("ex2.approx.ftz.f32 %0, %1;" : "=f"(y) : "f"(x));
    return y;
}

// ===========================================================================
// Prep: split 3 inputs (grid.y selects tensor); split 4 weights (grid.z)
// ===========================================================================
__global__ __launch_bounds__(256)
void split3(const float4* __restrict__ x0, const float4* __restrict__ x1,
            const float4* __restrict__ x2,
            __nv_bfloat16* __restrict__ h0, __nv_bfloat16* __restrict__ l0,
            __nv_bfloat16* __restrict__ h1, __nv_bfloat16* __restrict__ l1,
            __nv_bfloat16* __restrict__ h2, __nv_bfloat16* __restrict__ l2,
            int n4) {
    int i = blockIdx.x * blockDim.x + threadIdx.x;
    if (i >= n4) return;
    const int z = blockIdx.y;
    const float4* x = (z == 0) ? x0 : (z == 1) ? x1 : x2;
    __nv_bfloat16* hi = (z == 0) ? h0 : (z == 1) ? h1 : h2;
    __nv_bfloat16* lo = (z == 0) ? l0 : (z == 1) ? l1 : l2;
    float4 v = x[i];
    float f[4] = {v.x, v.y, v.z, v.w};
    __nv_bfloat16 h[4], l[4];
#pragma unroll
    for (int j = 0; j < 4; ++j) {
        h[j] = __float2bfloat16_rn(f[j]);
        l[j] = __float2bfloat16_rn(f[j] - __bfloat162float(h[j]));
    }
    ((__nv_bfloat162*)hi)[i * 2 + 0] = __nv_bfloat162(h[0], h[1]);
    ((__nv_bfloat162*)hi)[i * 2 + 1] = __nv_bfloat162(h[2], h[3]);
    ((__nv_bfloat162*)lo)[i * 2 + 0] = __nv_bfloat162(l[0], l[1]);
    ((__nv_bfloat162*)lo)[i * 2 + 1] = __nv_bfloat162(l[2], l[3]);
}

__global__ __launch_bounds__(256)
void wtsplit4(const float* __restrict__ w0, const float* __restrict__ w1,
              const float* __restrict__ w2, const float* __restrict__ w3,
              __nv_bfloat16* __restrict__ hi4, __nv_bfloat16* __restrict__ lo4) {
    __shared__ float t[32][33];
    const int z = blockIdx.z;
    const float* W = (z == 0) ? w0 : (z == 1) ? w1 : (z == 2) ? w2 : w3;
    __nv_bfloat16* hi = hi4 + (size_t)z * DM_ * DM_;
    __nv_bfloat16* lo = lo4 + (size_t)z * DM_ * DM_;
    const int n0 = blockIdx.x * 32;
    const int k0 = blockIdx.y * 32;
    const int tx = threadIdx.x, ty = threadIdx.y;
#pragma unroll
    for (int i = 0; i < 4; ++i)
        t[ty + i * 8][tx] = W[(size_t)(k0 + ty + i * 8) * DM_ + n0 + tx];
    __syncthreads();
#pragma unroll
    for (int i = 0; i < 4; ++i) {
        float v = t[tx][ty + i * 8];
        __nv_bfloat16 h = __float2bfloat16_rn(v);
        __nv_bfloat16 l = __float2bfloat16_rn(v - __bfloat162float(h));
        size_t o = (size_t)(n0 + ty + i * 8) * DM_ + k0 + tx;
        hi[o] = h;
        lo[o] = l;
    }
}

// ===========================================================================
// HMMA GEMM body (bf16 hi/lo split x3):  C = A @ Wt^T + bias
// ===========================================================================
#define BM 128
#define BN 128
#define BK 32
#define NKT (DM_ / BK)            // 32
#define RSTRIDE 80
#define TILE_B (128 * RSTRIDE)    // 10240 B
#define STAGE_B (4 * TILE_B)
#define GEMM_SMEM (2 * STAGE_B)   // 81920 B

__device__ __forceinline__ void load_ktile(uint32_t sb, int kt, int stage,
                                           const __nv_bfloat16* Ahi,
                                           const __nv_bfloat16* Alo,
                                           const __nv_bfloat16* Bhi,
                                           const __nv_bfloat16* Blo,
                                           int rowBase, int colBase) {
    const int tid = threadIdx.x;
    const uint32_t base = sb + stage * STAGE_B;
    const __nv_bfloat16* srcs[4] = {
        Ahi + (size_t)rowBase * DM_ + kt * BK,
        Alo + (size_t)rowBase * DM_ + kt * BK,
        Bhi + (size_t)colBase * DM_ + kt * BK,
        Blo + (size_t)colBase * DM_ + kt * BK};
#pragma unroll
    for (int t = 0; t < 4; ++t) {
#pragma unroll
        for (int i = 0; i < 2; ++i) {
            int c = tid + i * 256;
            int r = c >> 2, ch = c & 3;
            cp16(base + t * TILE_B + r * RSTRIDE + ch * 16,
                 srcs[t] + (size_t)r * DM_ + ch * 8);
        }
    }
}

__device__ __forceinline__ void gemm_body(
    const __nv_bfloat16* __restrict__ Ahi, const __nv_bfloat16* __restrict__ Alo,
    const __nv_bfloat16* __restrict__ Bhi, const __nv_bfloat16* __restrict__ Blo,
    const float* __restrict__ bias, float* __restrict__ C,
    __nv_bfloat16* __restrict__ Chi, __nv_bfloat16* __restrict__ Clo,
    char* smem) {
    const uint32_t sb = smem_u32(smem);
    const int tid  = threadIdx.x;
    const int wid  = tid >> 5;
    const int lane = tid & 31;
    const int rowBase = blockIdx.y * BM;
    const int colBase = blockIdx.x * BN;

    const int mbase = (wid >> 1) * 32;
    const int nbase = (wid & 1) * 64;

    float acc[2][8][4];
#pragma unroll
    for (int i = 0; i < 2; ++i)
#pragma unroll
        for (int j = 0; j < 8; ++j)
#pragma unroll
            for (int q = 0; q < 4; ++q) acc[i][j][q] = 0.f;

    load_ktile(sb, 0, 0, Ahi, Alo, Bhi, Blo, rowBase, colBase);
    CP_COMMIT();

    const int a_row = lane & 15;
    const int a_kh  = (lane >> 4) << 4;
    const int b_row = ((lane >> 4) & 1) * 8 + (lane & 7);
    const int b_kh  = ((lane >> 3) & 1) << 4;

    for (int kt = 0; kt < NKT; ++kt) {
        const int cur = kt & 1;
        if (kt + 1 < NKT) {
            load_ktile(sb, kt + 1, cur ^ 1, Ahi, Alo, Bhi, Blo, rowBase, colBase);
            CP_COMMIT();
            CP_WAIT(1);
        } else {
            CP_WAIT(0);
        }
        __syncthreads();

        const uint32_t st = sb + cur * STAGE_B;
#pragma unroll
        for (int s = 0; s < 2; ++s) {
            const uint32_t ks = s * 32;
            uint32_t ah[2][4], al[2][4];
#pragma unroll
            for (int i = 0; i < 2; ++i) {
                uint32_t off = (mbase + i * 16 + a_row) * RSTRIDE + ks + a_kh;
                ldmx4(ah[i], st + 0 * TILE_B + off);
                ldmx4(al[i], st + 1 * TILE_B + off);
            }
            uint32_t bh[8][2], bl[8][2];
#pragma unroll
            for (int jp = 0; jp < 4; ++jp) {
                uint32_t off = (nbase + jp * 16 + b_row) * RSTRIDE + ks + b_kh;
                uint32_t th[4], tl[4];
                ldmx4(th, st + 2 * TILE_B + off);
                ldmx4(tl, st + 3 * TILE_B + off);
                bh[jp * 2][0] = th[0]; bh[jp * 2][1] = th[1];
                bh[jp * 2 + 1][0] = th[2]; bh[jp * 2 + 1][1] = th[3];
                bl[jp * 2][0] = tl[0]; bl[jp * 2][1] = tl[1];
                bl[jp * 2 + 1][0] = tl[2]; bl[jp * 2 + 1][1] = tl[3];
            }
#pragma unroll
            for (int i = 0; i < 2; ++i)
#pragma unroll
                for (int j = 0; j < 8; ++j) {
                    mma_bf16(acc[i][j], ah[i], bh[j]);
                    mma_bf16(acc[i][j], ah[i], bl[j]);
                    mma_bf16(acc[i][j], al[i], bh[j]);
                }
        }
        __syncthreads();
    }

#pragma unroll
    for (int i = 0; i < 2; ++i) {
        const int r0 = rowBase + mbase + i * 16 + (lane >> 2);
#pragma unroll
        for (int j = 0; j < 8; ++j) {
            const int col = colBase + nbase + j * 8 + (lane & 3) * 2;
            const float b0 = bias[col], b1 = bias[col + 1];
            float f0 = acc[i][j][0] + b0, f1 = acc[i][j][1] + b1;
            float f2 = acc[i][j][2] + b0, f3 = acc[i][j][3] + b1;
            if (C) {
                *(float2*)(C + (size_t)r0 * DM_ + col)       = make_float2(f0, f1);
                *(float2*)(C + (size_t)(r0 + 8) * DM_ + col) = make_float2(f2, f3);
            } else {
                uint32_t h01 = cvt_bf16x2(f1, f0);
                uint32_t h23 = cvt_bf16x2(f3, f2);
                float r0f = f0 - __uint_as_float(h01 << 16);
                float r1f = f1 - __uint_as_float(h01 & 0xFFFF0000u);
                float r2f = f2 - __uint_as_float(h23 << 16);
                float r3f = f3 - __uint_as_float(h23 & 0xFFFF0000u);
                uint32_t l01 = cvt_bf16x2(r1f, r0f);
                uint32_t l23 = cvt_bf16x2(r3f, r2f);
                *(uint32_t*)(Chi + (size_t)r0 * DM_ + col)       = h01;
                *(uint32_t*)(Chi + (size_t)(r0 + 8) * DM_ + col) = h23;
                *(uint32_t*)(Clo + (size_t)r0 * DM_ + col)       = l01;
                *(uint32_t*)(Clo + (size_t)(r0 + 8) * DM_ + col) = l23;
            }
        }
    }
}

// QKV batched GEMM: grid.z selects (input, weight, bias, output) tuple.
__global__ __launch_bounds__(256)
void gemm_qkv(const __nv_bfloat16* __restrict__ Ah0, const __nv_bfloat16* __restrict__ Al0,
              const __nv_bfloat16* __restrict__ Ah1, const __nv_bfloat16* __restrict__ Al1,
              const __nv_bfloat16* __restrict__ Ah2, const __nv_bfloat16* __restrict__ Al2,
              const __nv_bfloat16* __restrict__ Wh4, const __nv_bfloat16* __restrict__ Wl4,
              const float* __restrict__ b0, const float* __restrict__ b1,
              const float* __restrict__ b2,
              __nv_bfloat16* __restrict__ Ch0, __nv_bfloat16* __restrict__ Cl0,
              __nv_bfloat16* __restrict__ Ch1, __nv_bfloat16* __restrict__ Cl1,
              __nv_bfloat16* __restrict__ Ch2, __nv_bfloat16* __restrict__ Cl2) {
    extern __shared__ char smem[];
    const int z = blockIdx.z;
    const __nv_bfloat16* Ah = (z == 0) ? Ah0 : (z == 1) ? Ah1 : Ah2;
    const __nv_bfloat16* Al = (z == 0) ? Al0 : (z == 1) ? Al1 : Al2;
    const float* bias = (z == 0) ? b0 : (z == 1) ? b1 : b2;
    __nv_bfloat16* Ch = (z == 0) ? Ch0 : (z == 1) ? Ch1 : Ch2;
    __nv_bfloat16* Cl = (z == 0) ? Cl0 : (z == 1) ? Cl1 : Cl2;
    gemm_body(Ah, Al, Wh4 + (size_t)z * DM_ * DM_, Wl4 + (size_t)z * DM_ * DM_,
              bias, nullptr, Ch, Cl, smem);
}

// O-projection GEMM: fp32 output.
__global__ __launch_bounds__(256)
void gemm_o(const __nv_bfloat16* __restrict__ Ahi, const __nv_bfloat16* __restrict__ Alo,
            const __nv_bfloat16* __restrict__ Whi, const __nv_bfloat16* __restrict__ Wlo,
            const float* __restrict__ bias, float* __restrict__ C) {
    extern __shared__ char smem[];
    gemm_body(Ahi, Alo, Whi, Wlo, bias, C, nullptr, nullptr, smem);
}

// ===========================================================================
// Flash attention v2 on mma.sync (bf16 hi/lo x3).
// CTA: 128 q-rows x Dh=64, 8 warps each owning 16 full rows (no cross-warp
// softmax, no O-merge). Q frags cached in registers; Q smem recycled as 3rd
// stage of the KV cp.async ring.
// ===========================================================================
#define ATSB  144                 // padded row stride (72 bf16)
#define TTS   (64 * ATSB)         // 9216 B per 64x64 bf16 tile
#define STG2  (4 * TTS)           // Khi,Klo,Vhi,Vlo per stage = 36864
#define QTS   (128 * ATSB)        // 18432 B per 128x64 Q tile (hi or lo)
#define FA2_SMEM (3 * STG2)       // 110592

#define C2F 0.1803368801111204f   // log2(e)/8  (Dh=64 scale folded into exp2)

__device__ __forceinline__ void fa2_load(uint32_t dstBase,
    const __nv_bfloat16* Khi, const __nv_bfloat16* Klo,
    const __nv_bfloat16* Vhi, const __nv_bfloat16* Vlo,
    size_t rowStart, int k0, int colOff) {
    const int tid = threadIdx.x;
    const __nv_bfloat16* srcs[4] = {
        Khi + (rowStart + k0) * DM_ + colOff,
        Klo + (rowStart + k0) * DM_ + colOff,
        Vhi + (rowStart + k0) * DM_ + colOff,
        Vlo + (rowStart + k0) * DM_ + colOff};
#pragma unroll
    for (int i = 0; i < 8; ++i) {
        int c = tid + i * 256;           // 0..2047
        int t = c >> 9, r = (c >> 3) & 63, ch = c & 7;
        cp16(dstBase + t * TTS + r * ATSB + ch * 16,
             srcs[t] + (size_t)r * DM_ + ch * 8);
    }
}

__global__ __launch_bounds__(256)
void flash_mma2(const __nv_bfloat16* __restrict__ Qhi,
                const __nv_bfloat16* __restrict__ Qlo,
                const __nv_bfloat16* __restrict__ Khi,
                const __nv_bfloat16* __restrict__ Klo,
                const __nv_bfloat16* __restrict__ Vhi,
                const __nv_bfloat16* __restrict__ Vlo,
                __nv_bfloat16* __restrict__ AOh,
                __nv_bfloat16* __restrict__ AOl) {
    extern __shared__ char smem[];
    const uint32_t sb = smem_u32(smem);
    const int tid = threadIdx.x, wid = tid >> 5, lane = tid & 31;
    const int bh = blockIdx.y, b = bh >> 4, h = bh & 15;
    const int q0 = blockIdx.x * 128;
    const size_t rowStart = (size_t)b * S_;
    const int colOff = h * DH_;

    const uint32_t sQ = sb + 2 * STG2;   // Q staging (becomes KV stage 2)

    // ---- issue Q loads (group), then KV tiles 0,1 (groups) ----
    {
        const __nv_bfloat16* qs[2] = {Qhi + (rowStart + q0) * DM_ + colOff,
                                      Qlo + (rowStart + q0) * DM_ + colOff};
#pragma unroll
        for (int i = 0; i < 8; ++i) {
            int c = tid + i * 256;       // 0..2047
            int t = c >> 10, r = (c >> 3) & 127, ch = c & 7;
            cp16(sQ + t * QTS + r * ATSB + ch * 16,
                 qs[t] + (size_t)r * DM_ + ch * 8);
        }
    }
    CP_COMMIT();
    fa2_load(sb + 0 * STG2, Khi, Klo, Vhi, Vlo, rowStart, 0, colOff);
    CP_COMMIT();
    fa2_load(sb + 1 * STG2, Khi, Klo, Vhi, Vlo, rowStart, 64, colOff);
    CP_COMMIT();
    CP_WAIT(2);                          // Q complete
    __syncthreads();

    // fragment addressing
    const int a_row = lane & 15;
    const int a_kh  = (lane >> 4) << 4;
    const int b_row = ((lane >> 4) & 1) * 8 + (lane & 7);
    const int b_kh  = ((lane >> 3) & 1) << 4;
    const int v_k   = (lane & 7) + ((lane >> 3) & 1) * 8;
    const int v_d8  = ((lane >> 4) & 1) * 8;

    // ---- Q fragments into registers (held for whole kernel) ----
    uint32_t qh[4][4], ql[4][4];
    {
        const uint32_t qbase = sQ + (16 * wid + a_row) * ATSB + a_kh;
#pragma unroll
        for (int ks = 0; ks < 4; ++ks) {
            ldmx4(qh[ks], qbase + ks * 32);
            ldmx4(ql[ks], qbase + QTS + ks * 32);
        }
    }
    __syncthreads();                     // all warps done with Q smem

    float m0 = -1e30f, m1 = -1e30f, l0 = 0.f, l1 = 0.f;
    float o[8][4];
#pragma unroll
    for (int j = 0; j < 8; ++j)
#pragma unroll
        for (int q = 0; q < 4; ++q) o[j][q] = 0.f;

    for (int jt = 0; jt < S_ / 64; ++jt) {
        if (jt < S_ / 64 - 1) { CP_WAIT(1); } else { CP_WAIT(0); }
        __syncthreads();                 // tile jt visible; prior stage free
        if (jt + 2 < S_ / 64) {
            fa2_load(sb + ((jt + 2) % 3) * STG2, Khi, Klo, Vhi, Vlo,
                     rowStart, (jt + 2) * 64, colOff);
            CP_COMMIT();
        }
        const uint32_t kvb = sb + (jt % 3) * STG2;

        // ---- scores: S = Q K^T (x3 hi/lo passes) ----
        float s[8][4];
#pragma unroll
        for (int j = 0; j < 8; ++j)
#pragma unroll
            for (int q = 0; q < 4; ++q) s[j][q] = 0.f;

#pragma unroll
        for (int ks = 0; ks < 4; ++ks) {
#pragma unroll
            for (int ntp = 0; ntp < 4; ++ntp) {
                uint32_t th[4], tl[4];
                const uint32_t addr = kvb + (ntp * 16 + b_row) * ATSB +
                                      ks * 32 + b_kh;
                ldmx4(th, addr);
                ldmx4(tl, addr + TTS);
                uint32_t k0h[2] = {th[0], th[1]}, k1h[2] = {th[2], th[3]};
                uint32_t k0l[2] = {tl[0], tl[1]}, k1l[2] = {tl[2], tl[3]};
                mma_bf16(s[2 * ntp], qh[ks], k0h);
                mma_bf16(s[2 * ntp], qh[ks], k0l);
                mma_bf16(s[2 * ntp], ql[ks], k0h);
                mma_bf16(s[2 * ntp + 1], qh[ks], k1h);
                mma_bf16(s[2 * ntp + 1], qh[ks], k1l);
                mma_bf16(s[2 * ntp + 1], ql[ks], k1h);
            }
        }

        // ---- online softmax (warp-private rows; quad shuffles only) ----
        float rmax0 = -1e30f, rmax1 = -1e30f;
#pragma unroll
        for (int j = 0; j < 8; ++j) {
            rmax0 = fmaxf(rmax0, fmaxf(s[j][0], s[j][1]));
            rmax1 = fmaxf(rmax1, fmaxf(s[j][2], s[j][3]));
        }
        rmax0 = fmaxf(rmax0, __shfl_xor_sync(0xffffffffu, rmax0, 1));
        rmax0 = fmaxf(rmax0, __shfl_xor_sync(0xffffffffu, rmax0, 2));
        rmax1 = fmaxf(rmax1, __shfl_xor_sync(0xffffffffu, rmax1, 1));
        rmax1 = fmaxf(rmax1, __shfl_xor_sync(0xffffffffu, rmax1, 2));
        const float m0n = fmaxf(m0, rmax0);
        const float m1n = fmaxf(m1, rmax1);
        const float c0 = ex2f((m0 - m0n) * C2F);
        const float c1 = ex2f((m1 - m1n) * C2F);
        m0 = m0n; m1 = m1n;
#pragma unroll
        for (int j = 0; j < 8; ++j) {
            o[j][0] *= c0; o[j][1] *= c0;
            o[j][2] *= c1; o[j][3] *= c1;
        }
        float sum0 = 0.f, sum1 = 0.f;
#pragma unroll
        for (int j = 0; j < 8; ++j) {
            s[j][0] = ex2f((s[j][0] - m0) * C2F);
            s[j][1] = ex2f((s[j][1] - m0) * C2F);
            s[j][2] = ex2f((s[j][2] - m1) * C2F);
            s[j][3] = ex2f((s[j][3] - m1) * C2F);
            sum0 += s[j][0] + s[j][1];
            sum1 += s[j][2] + s[j][3];
        }
        sum0 += __shfl_xor_sync(0xffffffffu, sum0, 1);
        sum0 += __shfl_xor_sync(0xffffffffu, sum0, 2);
        sum1 += __shfl_xor_sync(0xffffffffu, sum1, 1);
        sum1 += __shfl_xor_sync(0xffffffffu, sum1, 2);
        l0 = l0 * c0 + sum0;
        l1 = l1 * c1 + sum1;

        // ---- pack P into bf16 hi/lo A-fragments ----
        uint32_t PHa[8], PHb[8], PLa[8], PLb[8];
#pragma unroll
        for (int j = 0; j < 8; ++j) {
            PHa[j] = cvt_bf16x2(s[j][1], s[j][0]);
            PHb[j] = cvt_bf16x2(s[j][3], s[j][2]);
            float ra0 = s[j][0] - __uint_as_float(PHa[j] << 16);
            float ra1 = s[j][1] - __uint_as_float(PHa[j] & 0xFFFF0000u);
            float rb0 = s[j][2] - __uint_as_float(PHb[j] << 16);
            float rb1 = s[j][3] - __uint_as_float(PHb[j] & 0xFFFF0000u);
            PLa[j] = cvt_bf16x2(ra1, ra0);
            PLb[j] = cvt_bf16x2(rb1, rb0);
        }

        // ---- O += P @ V (x3 hi/lo passes, V^T frags via ldmatrix.trans) ----
#pragma unroll
        for (int ks = 0; ks < 4; ++ks) {
            uint32_t ah[4] = {PHa[2 * ks], PHb[2 * ks],
                              PHa[2 * ks + 1], PHb[2 * ks + 1]};
            uint32_t al[4] = {PLa[2 * ks], PLb[2 * ks],
                              PLa[2 * ks + 1], PLb[2 * ks + 1]};
#pragma unroll
            for (int dt = 0; dt < 4; ++dt) {
                const uint32_t addr = kvb + 2 * TTS + (16 * ks + v_k) * ATSB +
                                      (dt * 16 + v_d8) * 2;
                uint32_t vh[4], vl[4];
                ldmx4t(vh, addr);
                ldmx4t(vl, addr + TTS);
                uint32_t b0h[2] = {vh[0], vh[1]}, b1h[2] = {vh[2], vh[3]};
                uint32_t b0l[2] = {vl[0], vl[1]}, b1l[2] = {vl[2], vl[3]};
                mma_bf16(o[2 * dt], ah, b0h);
                mma_bf16(o[2 * dt], ah, b0l);
                mma_bf16(o[2 * dt], al, b0h);
                mma_bf16(o[2 * dt + 1], ah, b1h);
                mma_bf16(o[2 * dt + 1], ah, b1l);
                mma_bf16(o[2 * dt + 1], al, b1h);
            }
        }
    }

    // ---- normalize, split to bf16 hi/lo, write ----
    const float i0 = 1.f / l0, i1 = 1.f / l1;
    const size_t row0 = rowStart + q0 + 16 * wid + (lane >> 2);
    const size_t row1 = row0 + 8;
#pragma unroll
    for (int j = 0; j < 8; ++j) {
        const int col = colOff + j * 8 + (lane & 3) * 2;
        float f0 = o[j][0] * i0, f1 = o[j][1] * i0;
        float f2 = o[j][2] * i1, f3 = o[j][3] * i1;
        uint32_t h01 = cvt_bf16x2(f1, f0);
        uint32_t h23 = cvt_bf16x2(f3, f2);
        float r0f = f0 - __uint_as_float(h01 << 16);
        float r1f = f1 - __uint_as_float(h01 & 0xFFFF0000u);
        float r2f = f2 - __uint_as_float(h23 << 16);
        float r3f = f3 - __uint_as_float(h23 & 0xFFFF0000u);
        uint32_t l01 = cvt_bf16x2(r1f, r0f);
        uint32_t l23 = cvt_bf16x2(r3f, r2f);
        *(uint32_t*)(AOh + row0 * DM_ + col) = h01;
        *(uint32_t*)(AOh + row1 * DM_ + col) = h23;
        *(uint32_t*)(AOl + row0 * DM_ + col) = l01;
        *(uint32_t*)(AOl + row1 * DM_ + col) = l23;
    }
}

// ===========================================================================
// Launch
// ===========================================================================
extern "C" void kernel_launch(void* const* d_in, const int* in_sizes, int n_in,
                              void* d_out, int out_size)
{
    const float* query = (const float*)d_in[0];
    const float* key   = (const float*)d_in[1];
    const float* value = (const float*)d_in[2];
    const float* Wq    = (const float*)d_in[3];
    const float* bq    = (const float*)d_in[4];
    const float* Wk    = (const float*)d_in[5];
    const float* bk    = (const float*)d_in[6];
    const float* Wv    = (const float*)d_in[7];
    const float* bv    = (const float*)d_in[8];
    const float* Wo    = (const float*)d_in[9];
    const float* bo    = (const float*)d_in[10];
    float* out = (float*)d_out;

    __nv_bfloat16 *pIh, *pIl, *pWh, *pWl;
    __nv_bfloat16 *pQh, *pQl, *pKh, *pKl, *pVh, *pVl, *pAOh, *pAOl;
    cudaGetSymbolAddress((void**)&pIh,  g_Ih);
    cudaGetSymbolAddress((void**)&pIl,  g_Il);
    cudaGetSymbolAddress((void**)&pWh,  g_W4h);
    cudaGetSymbolAddress((void**)&pWl,  g_W4l);
    cudaGetSymbolAddress((void**)&pQh,  g_Qh);
    cudaGetSymbolAddress((void**)&pQl,  g_Ql);
    cudaGetSymbolAddress((void**)&pKh,  g_Kh);
    cudaGetSymbolAddress((void**)&pKl,  g_Kl);
    cudaGetSymbolAddress((void**)&pVh,  g_Vh);
    cudaGetSymbolAddress((void**)&pVl,  g_Vl);
    cudaGetSymbolAddress((void**)&pAOh, g_AOh);
    cudaGetSymbolAddress((void**)&pAOl, g_AOl);

    const size_t NTOK = (size_t)ROWS_ * DM_;

    static bool attrs_set = false;
    if (!attrs_set) {
        cudaFuncSetAttribute(gemm_qkv, cudaFuncAttributeMaxDynamicSharedMemorySize, GEMM_SMEM);
        cudaFuncSetAttribute(gemm_o,   cudaFuncAttributeMaxDynamicSharedMemorySize, GEMM_SMEM);
        cudaFuncSetAttribute(flash_mma2, cudaFuncAttributeMaxDynamicSharedMemorySize, FA2_SMEM);
        attrs_set = true;
    }

    const int n4 = ROWS_ * DM_ / 4;

    // 1) split all three inputs
    split3<<<dim3((n4 + 255) / 256, 3), 256>>>(
        (const float4*)query, (const float4*)key, (const float4*)value,
        pIh + 0 * NTOK, pIl + 0 * NTOK,
        pIh + 1 * NTOK, pIl + 1 * NTOK,
        pIh + 2 * NTOK, pIl + 2 * NTOK, n4);

    // 2) split+transpose all four weights
    wtsplit4<<<dim3(32, 32, 4), dim3(32, 8)>>>(Wq, Wk, Wv, Wo, pWh, pWl);

    // 3) Q,K,V projections (batched, epilogue -> bf16 hi/lo)
    gemm_qkv<<<dim3(DM_ / BN, ROWS_ / BM, 3), 256, GEMM_SMEM>>>(
        pIh + 0 * NTOK, pIl + 0 * NTOK,
        pIh + 1 * NTOK, pIl + 1 * NTOK,
        pIh + 2 * NTOK, pIl + 2 * NTOK,
        pWh, pWl, bq, bk, bv,
        pQh, pQl, pKh, pKl, pVh, pVl);

    // 4) attention (writes bf16 hi/lo)
    flash_mma2<<<dim3(S_ / 128, B_ * NH_), 256, FA2_SMEM>>>(
        pQh, pQl, pKh, pKl, pVh, pVl, pAOh, pAOl);

    // 5) output projection (fp32 result)
    gemm_o<<<dim3(DM_ / BN, ROWS_ / BM), 256, GEMM_SMEM>>>(
        pAOh, pAOl,
        pWh + 3 * (size_t)DM_ * DM_, pWl + 3 * (size_t)DM_ * DM_,
        bo, out);
}

// round 6
// speedup vs baseline: 3.2902x; 1.0567x over previous
#include <cuda_runtime.h>
#include <cuda_bf16.h>
#include <math.h>
#include <cstdint>

// ---------------------------------------------------------------------------
// Problem constants
// ---------------------------------------------------------------------------
#define B_    4
#define S_    2048
#define DM_   1024
#define NH_   16
#define DH_   64
#define ROWS_ (B_ * S_)          // 8192

// ---------------------------------------------------------------------------
// Scratch (device globals: allocation-free per harness rules)
// ---------------------------------------------------------------------------
__device__ __nv_bfloat16 g_Ih[3][ROWS_ * DM_];   // split inputs (q,k,v) hi
__device__ __nv_bfloat16 g_Il[3][ROWS_ * DM_];   // split inputs lo
__device__ __nv_bfloat16 g_W4h[4][DM_ * DM_];    // W^T hi (q,k,v,o)
__device__ __nv_bfloat16 g_W4l[4][DM_ * DM_];    // W^T lo
__device__ __nv_bfloat16 g_Qh[ROWS_ * DM_];
__device__ __nv_bfloat16 g_Ql[ROWS_ * DM_];
__device__ __nv_bfloat16 g_Kh[ROWS_ * DM_];
__device__ __nv_bfloat16 g_Kl[ROWS_ * DM_];
__device__ __nv_bfloat16 g_Vh[ROWS_ * DM_];
__device__ __nv_bfloat16 g_Vl[ROWS_ * DM_];
__device__ __nv_bfloat16 g_AOh[ROWS_ * DM_];
__device__ __nv_bfloat16 g_AOl[ROWS_ * DM_];

// ===========================================================================
// Generic-PTX helpers (legal on plain sm_103 target: sm_80+ instructions)
// ===========================================================================
__device__ __forceinline__ uint32_t smem_u32(const void* p) {
    uint32_t a;
    asm("{ .reg .u64 t; cvta.to.shared.u64 t, %1; cvt.u32.u64 %0, t; }"
        : "=r"(a) : "l"(p));
    return a;
}

__device__ __forceinline__ void cp16(uint32_t s, const void* g) {
    asm volatile("cp.async.cg.shared.global [%0], [%1], 16;" :: "r"(s), "l"(g));
}
#define CP_COMMIT() asm volatile("cp.async.commit_group;" ::: "memory")
#define CP_WAIT(n)  asm volatile("cp.async.wait_group %0;" :: "n"(n) : "memory")

__device__ __forceinline__ void ldmx4(uint32_t* r, uint32_t addr) {
    asm volatile("ldmatrix.sync.aligned.m8n8.x4.shared.b16 {%0,%1,%2,%3}, [%4];"
                 : "=r"(r[0]), "=r"(r[1]), "=r"(r[2]), "=r"(r[3]) : "r"(addr));
}

__device__ __forceinline__ void ldmx4t(uint32_t* r, uint32_t addr) {
    asm volatile("ldmatrix.sync.aligned.m8n8.x4.trans.shared.b16 {%0,%1,%2,%3}, [%4];"
                 : "=r"(r[0]), "=r"(r[1]), "=r"(r[2]), "=r"(r[3]) : "r"(addr));
}

__device__ __forceinline__ void mma_bf16(float* d, const uint32_t* a,
                                         const uint32_t* b) {
    asm volatile(
        "mma.sync.aligned.m16n8k16.row.col.f32.bf16.bf16.f32 "
        "{%0,%1,%2,%3}, {%4,%5,%6,%7}, {%8,%9}, {%0,%1,%2,%3};"
        : "+f"(d[0]), "+f"(d[1]), "+f"(d[2]), "+f"(d[3])
        : "r"(a[0]), "r"(a[1]), "r"(a[2]), "r"(a[3]), "r"(b[0]), "r"(b[1]));
}

__device__ __forceinline__ uint32_t cvt_bf16x2(float hi_elem, float lo_elem) {
    uint32_t r;
    asm("cvt.rn.satfinite.bf16x2.f32 %0, %1, %2;"
        : "=r"(r) : "f"(hi_elem), "f"(lo_elem));
    return r;
}

__device__ __forceinline__ float ex2f(float x) {
    float y;
    asm("ex2.approx.ftz.f32 %0, %1;" : "=f"(y) : "f"(x));
    return y;
}

// ===========================================================================
// Prep: split 3 inputs (grid.y selects tensor); split 4 weights (grid.z)
// ===========================================================================
__global__ __launch_bounds__(256)
void split3(const float4* __restrict__ x0, const float4* __restrict__ x1,
            const float4* __restrict__ x2,
            __nv_bfloat16* __restrict__ h0, __nv_bfloat16* __restrict__ l0,
            __nv_bfloat16* __restrict__ h1, __nv_bfloat16* __restrict__ l1,
            __nv_bfloat16* __restrict__ h2, __nv_bfloat16* __restrict__ l2,
            int n4) {
    int i = blockIdx.x * blockDim.x + threadIdx.x;
    if (i >= n4) return;
    const int z = blockIdx.y;
    const float4* x = (z == 0) ? x0 : (z == 1) ? x1 : x2;
    __nv_bfloat16* hi = (z == 0) ? h0 : (z == 1) ? h1 : h2;
    __nv_bfloat16* lo = (z == 0) ? l0 : (z == 1) ? l1 : l2;
    float4 v = x[i];
    float f[4] = {v.x, v.y, v.z, v.w};
    __nv_bfloat16 h[4], l[4];
#pragma unroll
    for (int j = 0; j < 4; ++j) {
        h[j] = __float2bfloat16_rn(f[j]);
        l[j] = __float2bfloat16_rn(f[j] - __bfloat162float(h[j]));
    }
    ((__nv_bfloat162*)hi)[i * 2 + 0] = __nv_bfloat162(h[0], h[1]);
    ((__nv_bfloat162*)hi)[i * 2 + 1] = __nv_bfloat162(h[2], h[3]);
    ((__nv_bfloat162*)lo)[i * 2 + 0] = __nv_bfloat162(l[0], l[1]);
    ((__nv_bfloat162*)lo)[i * 2 + 1] = __nv_bfloat162(l[2], l[3]);
}

__global__ __launch_bounds__(256)
void wtsplit4(const float* __restrict__ w0, const float* __restrict__ w1,
              const float* __restrict__ w2, const float* __restrict__ w3,
              __nv_bfloat16* __restrict__ hi4, __nv_bfloat16* __restrict__ lo4) {
    __shared__ float t[32][33];
    const int z = blockIdx.z;
    const float* W = (z == 0) ? w0 : (z == 1) ? w1 : (z == 2) ? w2 : w3;
    __nv_bfloat16* hi = hi4 + (size_t)z * DM_ * DM_;
    __nv_bfloat16* lo = lo4 + (size_t)z * DM_ * DM_;
    const int n0 = blockIdx.x * 32;
    const int k0 = blockIdx.y * 32;
    const int tx = threadIdx.x, ty = threadIdx.y;
#pragma unroll
    for (int i = 0; i < 4; ++i)
        t[ty + i * 8][tx] = W[(size_t)(k0 + ty + i * 8) * DM_ + n0 + tx];
    __syncthreads();
#pragma unroll
    for (int i = 0; i < 4; ++i) {
        float v = t[tx][ty + i * 8];
        __nv_bfloat16 h = __float2bfloat16_rn(v);
        __nv_bfloat16 l = __float2bfloat16_rn(v - __bfloat162float(h));
        size_t o = (size_t)(n0 + ty + i * 8) * DM_ + k0 + tx;
        hi[o] = h;
        lo[o] = l;
    }
}

// ===========================================================================
// HMMA GEMM body (bf16 hi/lo split x3):  C = A @ Wt^T + bias
// Restructured inner loop for low live-register count; 2 CTAs/SM target.
// ===========================================================================
#define BM 128
#define BN 128
#define BK 32
#define NKT (DM_ / BK)            // 32
#define RSTRIDE 80
#define TILE_B (128 * RSTRIDE)    // 10240 B
#define STAGE_B (4 * TILE_B)
#define GEMM_SMEM (2 * STAGE_B)   // 81920 B

__device__ __forceinline__ void load_ktile(uint32_t sb, int kt, int stage,
                                           const __nv_bfloat16* Ahi,
                                           const __nv_bfloat16* Alo,
                                           const __nv_bfloat16* Bhi,
                                           const __nv_bfloat16* Blo,
                                           int rowBase, int colBase) {
    const int tid = threadIdx.x;
    const uint32_t base = sb + stage * STAGE_B;
    const __nv_bfloat16* srcs[4] = {
        Ahi + (size_t)rowBase * DM_ + kt * BK,
        Alo + (size_t)rowBase * DM_ + kt * BK,
        Bhi + (size_t)colBase * DM_ + kt * BK,
        Blo + (size_t)colBase * DM_ + kt * BK};
#pragma unroll
    for (int t = 0; t < 4; ++t) {
#pragma unroll
        for (int i = 0; i < 2; ++i) {
            int c = tid + i * 256;
            int r = c >> 2, ch = c & 3;
            cp16(base + t * TILE_B + r * RSTRIDE + ch * 16,
                 srcs[t] + (size_t)r * DM_ + ch * 8);
        }
    }
}

__device__ __forceinline__ void gemm_body(
    const __nv_bfloat16* __restrict__ Ahi, const __nv_bfloat16* __restrict__ Alo,
    const __nv_bfloat16* __restrict__ Bhi, const __nv_bfloat16* __restrict__ Blo,
    const float* __restrict__ bias, float* __restrict__ C,
    __nv_bfloat16* __restrict__ Chi, __nv_bfloat16* __restrict__ Clo,
    char* smem) {
    const uint32_t sb = smem_u32(smem);
    const int tid  = threadIdx.x;
    const int wid  = tid >> 5;
    const int lane = tid & 31;
    const int rowBase = blockIdx.y * BM;
    const int colBase = blockIdx.x * BN;

    const int mbase = (wid >> 1) * 32;
    const int nbase = (wid & 1) * 64;

    float acc[2][8][4];
#pragma unroll
    for (int i = 0; i < 2; ++i)
#pragma unroll
        for (int j = 0; j < 8; ++j)
#pragma unroll
            for (int q = 0; q < 4; ++q) acc[i][j][q] = 0.f;

    load_ktile(sb, 0, 0, Ahi, Alo, Bhi, Blo, rowBase, colBase);
    CP_COMMIT();

    const int a_row = lane & 15;
    const int a_kh  = (lane >> 4) << 4;
    const int b_row = ((lane >> 4) & 1) * 8 + (lane & 7);
    const int b_kh  = ((lane >> 3) & 1) << 4;

    for (int kt = 0; kt < NKT; ++kt) {
        const int cur = kt & 1;
        if (kt + 1 < NKT) {
            load_ktile(sb, kt + 1, cur ^ 1, Ahi, Alo, Bhi, Blo, rowBase, colBase);
            CP_COMMIT();
            CP_WAIT(1);
        } else {
            CP_WAIT(0);
        }
        __syncthreads();

        const uint32_t st = sb + cur * STAGE_B;
#pragma unroll
        for (int s = 0; s < 2; ++s) {
            const uint32_t ks = s * 32;
            uint32_t ah[2][4], al[2][4];
#pragma unroll
            for (int i = 0; i < 2; ++i) {
                uint32_t off = (mbase + i * 16 + a_row) * RSTRIDE + ks + a_kh;
                ldmx4(ah[i], st + 0 * TILE_B + off);
                ldmx4(al[i], st + 1 * TILE_B + off);
            }
            // B fragments loaded per-jp and consumed immediately (low live regs)
#pragma unroll
            for (int jp = 0; jp < 4; ++jp) {
                uint32_t off = (nbase + jp * 16 + b_row) * RSTRIDE + ks + b_kh;
                uint32_t th[4], tl[4];
                ldmx4(th, st + 2 * TILE_B + off);
                ldmx4(tl, st + 3 * TILE_B + off);
                uint32_t b0h[2] = {th[0], th[1]}, b1h[2] = {th[2], th[3]};
                uint32_t b0l[2] = {tl[0], tl[1]}, b1l[2] = {tl[2], tl[3]};
#pragma unroll
                for (int i = 0; i < 2; ++i) {
                    mma_bf16(acc[i][jp * 2],     ah[i], b0h);
                    mma_bf16(acc[i][jp * 2],     ah[i], b0l);
                    mma_bf16(acc[i][jp * 2],     al[i], b0h);
                    mma_bf16(acc[i][jp * 2 + 1], ah[i], b1h);
                    mma_bf16(acc[i][jp * 2 + 1], ah[i], b1l);
                    mma_bf16(acc[i][jp * 2 + 1], al[i], b1h);
                }
            }
        }
        __syncthreads();
    }

#pragma unroll
    for (int i = 0; i < 2; ++i) {
        const int r0 = rowBase + mbase + i * 16 + (lane >> 2);
#pragma unroll
        for (int j = 0; j < 8; ++j) {
            const int col = colBase + nbase + j * 8 + (lane & 3) * 2;
            const float b0 = bias[col], b1 = bias[col + 1];
            float f0 = acc[i][j][0] + b0, f1 = acc[i][j][1] + b1;
            float f2 = acc[i][j][2] + b0, f3 = acc[i][j][3] + b1;
            if (C) {
                *(float2*)(C + (size_t)r0 * DM_ + col)       = make_float2(f0, f1);
                *(float2*)(C + (size_t)(r0 + 8) * DM_ + col) = make_float2(f2, f3);
            } else {
                uint32_t h01 = cvt_bf16x2(f1, f0);
                uint32_t h23 = cvt_bf16x2(f3, f2);
                float r0f = f0 - __uint_as_float(h01 << 16);
                float r1f = f1 - __uint_as_float(h01 & 0xFFFF0000u);
                float r2f = f2 - __uint_as_float(h23 << 16);
                float r3f = f3 - __uint_as_float(h23 & 0xFFFF0000u);
                uint32_t l01 = cvt_bf16x2(r1f, r0f);
                uint32_t l23 = cvt_bf16x2(r3f, r2f);
                *(uint32_t*)(Chi + (size_t)r0 * DM_ + col)       = h01;
                *(uint32_t*)(Chi + (size_t)(r0 + 8) * DM_ + col) = h23;
                *(uint32_t*)(Clo + (size_t)r0 * DM_ + col)       = l01;
                *(uint32_t*)(Clo + (size_t)(r0 + 8) * DM_ + col) = l23;
            }
        }
    }
}

__global__ __launch_bounds__(256, 2)
void gemm_qkv(const __nv_bfloat16* __restrict__ Ah0, const __nv_bfloat16* __restrict__ Al0,
              const __nv_bfloat16* __restrict__ Ah1, const __nv_bfloat16* __restrict__ Al1,
              const __nv_bfloat16* __restrict__ Ah2, const __nv_bfloat16* __restrict__ Al2,
              const __nv_bfloat16* __restrict__ Wh4, const __nv_bfloat16* __restrict__ Wl4,
              const float* __restrict__ b0, const float* __restrict__ b1,
              const float* __restrict__ b2,
              __nv_bfloat16* __restrict__ Ch0, __nv_bfloat16* __restrict__ Cl0,
              __nv_bfloat16* __restrict__ Ch1, __nv_bfloat16* __restrict__ Cl1,
              __nv_bfloat16* __restrict__ Ch2, __nv_bfloat16* __restrict__ Cl2) {
    extern __shared__ char smem[];
    const int z = blockIdx.z;
    const __nv_bfloat16* Ah = (z == 0) ? Ah0 : (z == 1) ? Ah1 : Ah2;
    const __nv_bfloat16* Al = (z == 0) ? Al0 : (z == 1) ? Al1 : Al2;
    const float* bias = (z == 0) ? b0 : (z == 1) ? b1 : b2;
    __nv_bfloat16* Ch = (z == 0) ? Ch0 : (z == 1) ? Ch1 : Ch2;
    __nv_bfloat16* Cl = (z == 0) ? Cl0 : (z == 1) ? Cl1 : Cl2;
    gemm_body(Ah, Al, Wh4 + (size_t)z * DM_ * DM_, Wl4 + (size_t)z * DM_ * DM_,
              bias, nullptr, Ch, Cl, smem);
}

__global__ __launch_bounds__(256, 2)
void gemm_o(const __nv_bfloat16* __restrict__ Ahi, const __nv_bfloat16* __restrict__ Alo,
            const __nv_bfloat16* __restrict__ Whi, const __nv_bfloat16* __restrict__ Wlo,
            const float* __restrict__ bias, float* __restrict__ C) {
    extern __shared__ char smem[];
    gemm_body(Ahi, Alo, Whi, Wlo, bias, C, nullptr, nullptr, smem);
}

// ===========================================================================
// Flash attention v3 on mma.sync (bf16 hi/lo x3), 2 CTAs/SM.
// CTA: 128 q-rows, 8 warps each owning 16 full rows.
// Q-hi fragments in registers; Q-lo persistent in smem (reloaded per tile).
// 2-stage KV cp.async ring. smem 90 KB, regs target <=128.
// ===========================================================================
#define ATSB  144                 // padded row stride (72 bf16)
#define TTS   (64 * ATSB)         // 9216 B per 64x64 bf16 tile
#define STG2  (4 * TTS)           // Khi,Klo,Vhi,Vlo per stage = 36864
#define QTS   (128 * ATSB)        // 18432 B per 128x64 Q tile
#define FA3_SMEM (2 * STG2 + QTS) // 92160

#define C2F 0.1803368801111204f   // log2(e)/8  (Dh=64 scale folded into exp2)

__device__ __forceinline__ void fa2_load(uint32_t dstBase,
    const __nv_bfloat16* Khi, const __nv_bfloat16* Klo,
    const __nv_bfloat16* Vhi, const __nv_bfloat16* Vlo,
    size_t rowStart, int k0, int colOff) {
    const int tid = threadIdx.x;
    const __nv_bfloat16* srcs[4] = {
        Khi + (rowStart + k0) * DM_ + colOff,
        Klo + (rowStart + k0) * DM_ + colOff,
        Vhi + (rowStart + k0) * DM_ + colOff,
        Vlo + (rowStart + k0) * DM_ + colOff};
#pragma unroll
    for (int i = 0; i < 8; ++i) {
        int c = tid + i * 256;           // 0..2047
        int t = c >> 9, r = (c >> 3) & 63, ch = c & 7;
        cp16(dstBase + t * TTS + r * ATSB + ch * 16,
             srcs[t] + (size_t)r * DM_ + ch * 8);
    }
}

__global__ __launch_bounds__(256, 2)
void flash_mma3(const __nv_bfloat16* __restrict__ Qhi,
                const __nv_bfloat16* __restrict__ Qlo,
                const __nv_bfloat16* __restrict__ Khi,
                const __nv_bfloat16* __restrict__ Klo,
                const __nv_bfloat16* __restrict__ Vhi,
                const __nv_bfloat16* __restrict__ Vlo,
                __nv_bfloat16* __restrict__ AOh,
                __nv_bfloat16* __restrict__ AOl) {
    extern __shared__ char smem[];
    const uint32_t sb = smem_u32(smem);
    const int tid = threadIdx.x, wid = tid >> 5, lane = tid & 31;
    const int bh = blockIdx.y, b = bh >> 4, h = bh & 15;
    const int q0 = blockIdx.x * 128;
    const size_t rowStart = (size_t)b * S_;
    const int colOff = h * DH_;

    const uint32_t sQlo = sb + 2 * STG2;    // persistent Q-lo
    const uint32_t sQhiStage = sb + STG2;   // Q-hi staged in KV stage 1

    // ---- group A: Qhi -> stage1 region, Qlo -> persistent region ----
    {
        const __nv_bfloat16* qh_src = Qhi + (rowStart + q0) * DM_ + colOff;
        const __nv_bfloat16* ql_src = Qlo + (rowStart + q0) * DM_ + colOff;
#pragma unroll
        for (int i = 0; i < 4; ++i) {
            int c = tid + i * 256;       // 0..1023: r 0..127, ch 0..7
            int r = c >> 3, ch = c & 7;
            cp16(sQhiStage + r * ATSB + ch * 16, qh_src + (size_t)r * DM_ + ch * 8);
            cp16(sQlo      + r * ATSB + ch * 16, ql_src + (size_t)r * DM_ + ch * 8);
        }
    }
    CP_COMMIT();
    // group B: KV tile 0 -> stage 0
    fa2_load(sb, Khi, Klo, Vhi, Vlo, rowStart, 0, colOff);
    CP_COMMIT();
    CP_WAIT(1);                          // Q complete (group A)
    __syncthreads();

    // fragment addressing
    const int a_row = lane & 15;
    const int a_kh  = (lane >> 4) << 4;
    const int b_row = ((lane >> 4) & 1) * 8 + (lane & 7);
    const int b_kh  = ((lane >> 3) & 1) << 4;
    const int v_k   = (lane & 7) + ((lane >> 3) & 1) * 8;
    const int v_d8  = ((lane >> 4) & 1) * 8;

    // ---- Q-hi fragments into registers ----
    uint32_t qh[4][4];
    const uint32_t qfoff = (16 * wid + a_row) * ATSB + a_kh;
#pragma unroll
    for (int ks = 0; ks < 4; ++ks)
        ldmx4(qh[ks], sQhiStage + qfoff + ks * 32);
    __syncthreads();                     // stage-1 region free again

    // group C: KV tile 1 -> stage 1
    fa2_load(sb + STG2, Khi, Klo, Vhi, Vlo, rowStart, 64, colOff);
    CP_COMMIT();

    float m0 = -1e30f, m1 = -1e30f, l0 = 0.f, l1 = 0.f;
    float o[8][4];
#pragma unroll
    for (int j = 0; j < 8; ++j)
#pragma unroll
        for (int q = 0; q < 4; ++q) o[j][q] = 0.f;

    for (int jt = 0; jt < S_ / 64; ++jt) {
        if (jt < S_ / 64 - 1) { CP_WAIT(1); } else { CP_WAIT(0); }
        __syncthreads();                 // tile jt resident in stage jt&1
        const uint32_t kvb = sb + (jt & 1) * STG2;

        // ---- scores: S = Q K^T (x3 hi/lo passes; Q-lo from smem) ----
        float s[8][4];
#pragma unroll
        for (int j = 0; j < 8; ++j)
#pragma unroll
            for (int q = 0; q < 4; ++q) s[j][q] = 0.f;

#pragma unroll
        for (int ks = 0; ks < 4; ++ks) {
            uint32_t ql[4];
            ldmx4(ql, sQlo + qfoff + ks * 32);
#pragma unroll
            for (int ntp = 0; ntp < 4; ++ntp) {
                uint32_t th[4], tl[4];
                const uint32_t addr = kvb + (ntp * 16 + b_row) * ATSB +
                                      ks * 32 + b_kh;
                ldmx4(th, addr);
                ldmx4(tl, addr + TTS);
                uint32_t k0h[2] = {th[0], th[1]}, k1h[2] = {th[2], th[3]};
                uint32_t k0l[2] = {tl[0], tl[1]}, k1l[2] = {tl[2], tl[3]};
                mma_bf16(s[2 * ntp], qh[ks], k0h);
                mma_bf16(s[2 * ntp], qh[ks], k0l);
                mma_bf16(s[2 * ntp], ql, k0h);
                mma_bf16(s[2 * ntp + 1], qh[ks], k1h);
                mma_bf16(s[2 * ntp + 1], qh[ks], k1l);
                mma_bf16(s[2 * ntp + 1], ql, k1h);
            }
        }

        // ---- online softmax (warp-private rows; quad shuffles only) ----
        float rmax0 = -1e30f, rmax1 = -1e30f;
#pragma unroll
        for (int j = 0; j < 8; ++j) {
            rmax0 = fmaxf(rmax0, fmaxf(s[j][0], s[j][1]));
            rmax1 = fmaxf(rmax1, fmaxf(s[j][2], s[j][3]));
        }
        rmax0 = fmaxf(rmax0, __shfl_xor_sync(0xffffffffu, rmax0, 1));
        rmax0 = fmaxf(rmax0, __shfl_xor_sync(0xffffffffu, rmax0, 2));
        rmax1 = fmaxf(rmax1, __shfl_xor_sync(0xffffffffu, rmax1, 1));
        rmax1 = fmaxf(rmax1, __shfl_xor_sync(0xffffffffu, rmax1, 2));
        const float m0n = fmaxf(m0, rmax0);
        const float m1n = fmaxf(m1, rmax1);
        const float c0 = ex2f((m0 - m0n) * C2F);
        const float c1 = ex2f((m1 - m1n) * C2F);
        m0 = m0n; m1 = m1n;
#pragma unroll
        for (int j = 0; j < 8; ++j) {
            o[j][0] *= c0; o[j][1] *= c0;
            o[j][2] *= c1; o[j][3] *= c1;
        }
        float sum0 = 0.f, sum1 = 0.f;
#pragma unroll
        for (int j = 0; j < 8; ++j) {
            s[j][0] = ex2f((s[j][0] - m0) * C2F);
            s[j][1] = ex2f((s[j][1] - m0) * C2F);
            s[j][2] = ex2f((s[j][2] - m1) * C2F);
            s[j][3] = ex2f((s[j][3] - m1) * C2F);
            sum0 += s[j][0] + s[j][1];
            sum1 += s[j][2] + s[j][3];
        }
        sum0 += __shfl_xor_sync(0xffffffffu, sum0, 1);
        sum0 += __shfl_xor_sync(0xffffffffu, sum0, 2);
        sum1 += __shfl_xor_sync(0xffffffffu, sum1, 1);
        sum1 += __shfl_xor_sync(0xffffffffu, sum1, 2);
        l0 = l0 * c0 + sum0;
        l1 = l1 * c1 + sum1;

        // ---- pack P into bf16 hi/lo A-fragments (overwrites s) ----
        uint32_t PHa[8], PHb[8], PLa[8], PLb[8];
#pragma unroll
        for (int j = 0; j < 8; ++j) {
            PHa[j] = cvt_bf16x2(s[j][1], s[j][0]);
            PHb[j] = cvt_bf16x2(s[j][3], s[j][2]);
            float ra0 = s[j][0] - __uint_as_float(PHa[j] << 16);
            float ra1 = s[j][1] - __uint_as_float(PHa[j] & 0xFFFF0000u);
            float rb0 = s[j][2] - __uint_as_float(PHb[j] << 16);
            float rb1 = s[j][3] - __uint_as_float(PHb[j] & 0xFFFF0000u);
            PLa[j] = cvt_bf16x2(ra1, ra0);
            PLb[j] = cvt_bf16x2(rb1, rb0);
        }

        // ---- O += P @ V (x3 hi/lo passes, V^T frags via ldmatrix.trans) ----
#pragma unroll
        for (int ks = 0; ks < 4; ++ks) {
            uint32_t ah[4] = {PHa[2 * ks], PHb[2 * ks],
                              PHa[2 * ks + 1], PHb[2 * ks + 1]};
            uint32_t al[4] = {PLa[2 * ks], PLb[2 * ks],
                              PLa[2 * ks + 1], PLb[2 * ks + 1]};
#pragma unroll
            for (int dt = 0; dt < 4; ++dt) {
                const uint32_t addr = kvb + 2 * TTS + (16 * ks + v_k) * ATSB +
                                      (dt * 16 + v_d8) * 2;
                uint32_t vh[4], vl[4];
                ldmx4t(vh, addr);
                ldmx4t(vl, addr + TTS);
                uint32_t b0h[2] = {vh[0], vh[1]}, b1h[2] = {vh[2], vh[3]};
                uint32_t b0l[2] = {vl[0], vl[1]}, b1l[2] = {vl[2], vl[3]};
                mma_bf16(o[2 * dt], ah, b0h);
                mma_bf16(o[2 * dt], ah, b0l);
                mma_bf16(o[2 * dt], al, b0h);
                mma_bf16(o[2 * dt + 1], ah, b1h);
                mma_bf16(o[2 * dt + 1], ah, b1l);
                mma_bf16(o[2 * dt + 1], al, b1h);
            }
        }

        __syncthreads();                 // all reads of stage jt&1 done
        if (jt + 2 < S_ / 64) {          // prefetch jt+2 into freed stage
            fa2_load(sb + (jt & 1) * STG2, Khi, Klo, Vhi, Vlo,
                     rowStart, (jt + 2) * 64, colOff);
            CP_COMMIT();
        }
    }

    // ---- normalize, split to bf16 hi/lo, write ----
    const float i0 = 1.f / l0, i1 = 1.f / l1;
    const size_t row0 = rowStart + q0 + 16 * wid + (lane >> 2);
    const size_t row1 = row0 + 8;
#pragma unroll
    for (int j = 0; j < 8; ++j) {
        const int col = colOff + j * 8 + (lane & 3) * 2;
        float f0 = o[j][0] * i0, f1 = o[j][1] * i0;
        float f2 = o[j][2] * i1, f3 = o[j][3] * i1;
        uint32_t h01 = cvt_bf16x2(f1, f0);
        uint32_t h23 = cvt_bf16x2(f3, f2);
        float r0f = f0 - __uint_as_float(h01 << 16);
        float r1f = f1 - __uint_as_float(h01 & 0xFFFF0000u);
        float r2f = f2 - __uint_as_float(h23 << 16);
        float r3f = f3 - __uint_as_float(h23 & 0xFFFF0000u);
        uint32_t l01 = cvt_bf16x2(r1f, r0f);
        uint32_t l23 = cvt_bf16x2(r3f, r2f);
        *(uint32_t*)(AOh + row0 * DM_ + col) = h01;
        *(uint32_t*)(AOh + row1 * DM_ + col) = h23;
        *(uint32_t*)(AOl + row0 * DM_ + col) = l01;
        *(uint32_t*)(AOl + row1 * DM_ + col) = l23;
    }
}

// ===========================================================================
// Launch
// ===========================================================================
extern "C" void kernel_launch(void* const* d_in, const int* in_sizes, int n_in,
                              void* d_out, int out_size)
{
    const float* query = (const float*)d_in[0];
    const float* key   = (const float*)d_in[1];
    const float* value = (const float*)d_in[2];
    const float* Wq    = (const float*)d_in[3];
    const float* bq    = (const float*)d_in[4];
    const float* Wk    = (const float*)d_in[5];
    const float* bk    = (const float*)d_in[6];
    const float* Wv    = (const float*)d_in[7];
    const float* bv    = (const float*)d_in[8];
    const float* Wo    = (const float*)d_in[9];
    const float* bo    = (const float*)d_in[10];
    float* out = (float*)d_out;

    __nv_bfloat16 *pIh, *pIl, *pWh, *pWl;
    __nv_bfloat16 *pQh, *pQl, *pKh, *pKl, *pVh, *pVl, *pAOh, *pAOl;
    cudaGetSymbolAddress((void**)&pIh,  g_Ih);
    cudaGetSymbolAddress((void**)&pIl,  g_Il);
    cudaGetSymbolAddress((void**)&pWh,  g_W4h);
    cudaGetSymbolAddress((void**)&pWl,  g_W4l);
    cudaGetSymbolAddress((void**)&pQh,  g_Qh);
    cudaGetSymbolAddress((void**)&pQl,  g_Ql);
    cudaGetSymbolAddress((void**)&pKh,  g_Kh);
    cudaGetSymbolAddress((void**)&pKl,  g_Kl);
    cudaGetSymbolAddress((void**)&pVh,  g_Vh);
    cudaGetSymbolAddress((void**)&pVl,  g_Vl);
    cudaGetSymbolAddress((void**)&pAOh, g_AOh);
    cudaGetSymbolAddress((void**)&pAOl, g_AOl);

    const size_t NTOK = (size_t)ROWS_ * DM_;

    static bool attrs_set = false;
    if (!attrs_set) {
        cudaFuncSetAttribute(gemm_qkv, cudaFuncAttributeMaxDynamicSharedMemorySize, GEMM_SMEM);
        cudaFuncSetAttribute(gemm_o,   cudaFuncAttributeMaxDynamicSharedMemorySize, GEMM_SMEM);
        cudaFuncSetAttribute(flash_mma3, cudaFuncAttributeMaxDynamicSharedMemorySize, FA3_SMEM);
        attrs_set = true;
    }

    const int n4 = ROWS_ * DM_ / 4;

    // 1) split all three inputs
    split3<<<dim3((n4 + 255) / 256, 3), 256>>>(
        (const float4*)query, (const float4*)key, (const float4*)value,
        pIh + 0 * NTOK, pIl + 0 * NTOK,
        pIh + 1 * NTOK, pIl + 1 * NTOK,
        pIh + 2 * NTOK, pIl + 2 * NTOK, n4);

    // 2) split+transpose all four weights
    wtsplit4<<<dim3(32, 32, 4), dim3(32, 8)>>>(Wq, Wk, Wv, Wo, pWh, pWl);

    // 3) Q,K,V projections (batched, epilogue -> bf16 hi/lo)
    gemm_qkv<<<dim3(DM_ / BN, ROWS_ / BM, 3), 256, GEMM_SMEM>>>(
        pIh + 0 * NTOK, pIl + 0 * NTOK,
        pIh + 1 * NTOK, pIl + 1 * NTOK,
        pIh + 2 * NTOK, pIl + 2 * NTOK,
        pWh, pWl, bq, bk, bv,
        pQh, pQl, pKh, pKl, pVh, pVl);

    // 4) attention (writes bf16 hi/lo)
    flash_mma3<<<dim3(S_ / 128, B_ * NH_), 256, FA3_SMEM>>>(
        pQh, pQl, pKh, pKl, pVh, pVl, pAOh, pAOl);

    // 5) output projection (fp32 result)
    gemm_o<<<dim3(DM_ / BN, ROWS_ / BM), 256, GEMM_SMEM>>>(
        pAOh, pAOl,
        pWh + 3 * (size_t)DM_ * DM_, pWl + 3 * (size_t)DM_ * DM_,
        bo, out);
}

// round 7
// speedup vs baseline: 3.5665x; 1.0840x over previous
#include <cuda_runtime.h>
#include <cuda_bf16.h>
#include <math.h>
#include <cstdint>

// ---------------------------------------------------------------------------
// Problem constants
// ---------------------------------------------------------------------------
#define B_    4
#define S_    2048
#define DM_   1024
#define NH_   16
#define DH_   64
#define ROWS_ (B_ * S_)          // 8192

// ---------------------------------------------------------------------------
// Scratch (device globals: allocation-free per harness rules)
// ---------------------------------------------------------------------------
__device__ __nv_bfloat16 g_Ih[3][ROWS_ * DM_];   // split inputs (q,k,v) hi
__device__ __nv_bfloat16 g_Il[3][ROWS_ * DM_];   // split inputs lo
__device__ __nv_bfloat16 g_W4h[4][DM_ * DM_];    // W^T hi (q,k,v,o)
__device__ __nv_bfloat16 g_W4l[4][DM_ * DM_];    // W^T lo
__device__ __nv_bfloat16 g_Qh[ROWS_ * DM_];
__device__ __nv_bfloat16 g_Ql[ROWS_ * DM_];
__device__ __nv_bfloat16 g_Kh[ROWS_ * DM_];
__device__ __nv_bfloat16 g_Kl[ROWS_ * DM_];
__device__ __nv_bfloat16 g_Vh[ROWS_ * DM_];
__device__ __nv_bfloat16 g_Vl[ROWS_ * DM_];
__device__ __nv_bfloat16 g_AOh[ROWS_ * DM_];
__device__ __nv_bfloat16 g_AOl[ROWS_ * DM_];

// ===========================================================================
// Generic-PTX helpers (legal on plain sm_103 target: sm_80+ instructions)
// ===========================================================================
__device__ __forceinline__ uint32_t smem_u32(const void* p) {
    uint32_t a;
    asm("{ .reg .u64 t; cvta.to.shared.u64 t, %1; cvt.u32.u64 %0, t; }"
        : "=r"(a) : "l"(p));
    return a;
}

__device__ __forceinline__ void cp16(uint32_t s, const void* g) {
    asm volatile("cp.async.cg.shared.global [%0], [%1], 16;" :: "r"(s), "l"(g));
}
#define CP_COMMIT() asm volatile("cp.async.commit_group;" ::: "memory")
#define CP_WAIT(n)  asm volatile("cp.async.wait_group %0;" :: "n"(n) : "memory")

__device__ __forceinline__ void ldmx4(uint32_t* r, uint32_t addr) {
    asm volatile("ldmatrix.sync.aligned.m8n8.x4.shared.b16 {%0,%1,%2,%3}, [%4];"
                 : "=r"(r[0]), "=r"(r[1]), "=r"(r[2]), "=r"(r[3]) : "r"(addr));
}

__device__ __forceinline__ void ldmx4t(uint32_t* r, uint32_t addr) {
    asm volatile("ldmatrix.sync.aligned.m8n8.x4.trans.shared.b16 {%0,%1,%2,%3}, [%4];"
                 : "=r"(r[0]), "=r"(r[1]), "=r"(r[2]), "=r"(r[3]) : "r"(addr));
}

__device__ __forceinline__ void mma_bf16(float* d, const uint32_t* a,
                                         const uint32_t* b) {
    asm volatile(
        "mma.sync.aligned.m16n8k16.row.col.f32.bf16.bf16.f32 "
        "{%0,%1,%2,%3}, {%4,%5,%6,%7}, {%8,%9}, {%0,%1,%2,%3};"
        : "+f"(d[0]), "+f"(d[1]), "+f"(d[2]), "+f"(d[3])
        : "r"(a[0]), "r"(a[1]), "r"(a[2]), "r"(a[3]), "r"(b[0]), "r"(b[1]));
}

__device__ __forceinline__ uint32_t cvt_bf16x2(float hi_elem, float lo_elem) {
    uint32_t r;
    asm("cvt.rn.satfinite.bf16x2.f32 %0, %1, %2;"
        : "=r"(r) : "f"(hi_elem), "f"(lo_elem));
    return r;
}

__device__ __forceinline__ float ex2f(float x) {
    float y;
    asm("ex2.approx.ftz.f32 %0, %1;" : "=f"(y) : "f"(x));
    return y;
}

// XOR swizzles: conflict-free ldmatrix on unpadded rows.
// 128B rows (8x16B chunks): chunk ^= row&7.
#define SWZ128B(r, ch) ((((ch) ^ ((r) & 7)) << 4))
// 64B rows (4x16B chunks): chunk ^= (row>>1)&3 (half-row alternation covers 8).
#define SWZ64B(r, ch)  ((((ch) ^ (((r) >> 1) & 3)) << 4))

__device__ __forceinline__ int inc3(int x) { return (x == 2) ? 0 : x + 1; }

// ===========================================================================
// Prep: split 3 inputs (grid.y selects tensor); split 4 weights (grid.z)
// ===========================================================================
__global__ __launch_bounds__(256)
void split3(const float4* __restrict__ x0, const float4* __restrict__ x1,
            const float4* __restrict__ x2,
            __nv_bfloat16* __restrict__ h0, __nv_bfloat16* __restrict__ l0,
            __nv_bfloat16* __restrict__ h1, __nv_bfloat16* __restrict__ l1,
            __nv_bfloat16* __restrict__ h2, __nv_bfloat16* __restrict__ l2,
            int n4) {
    int i = blockIdx.x * blockDim.x + threadIdx.x;
    if (i >= n4) return;
    const int z = blockIdx.y;
    const float4* x = (z == 0) ? x0 : (z == 1) ? x1 : x2;
    __nv_bfloat16* hi = (z == 0) ? h0 : (z == 1) ? h1 : h2;
    __nv_bfloat16* lo = (z == 0) ? l0 : (z == 1) ? l1 : l2;
    float4 v = x[i];
    float f[4] = {v.x, v.y, v.z, v.w};
    __nv_bfloat16 h[4], l[4];
#pragma unroll
    for (int j = 0; j < 4; ++j) {
        h[j] = __float2bfloat16_rn(f[j]);
        l[j] = __float2bfloat16_rn(f[j] - __bfloat162float(h[j]));
    }
    ((__nv_bfloat162*)hi)[i * 2 + 0] = __nv_bfloat162(h[0], h[1]);
    ((__nv_bfloat162*)hi)[i * 2 + 1] = __nv_bfloat162(h[2], h[3]);
    ((__nv_bfloat162*)lo)[i * 2 + 0] = __nv_bfloat162(l[0], l[1]);
    ((__nv_bfloat162*)lo)[i * 2 + 1] = __nv_bfloat162(l[2], l[3]);
}

__global__ __launch_bounds__(256)
void wtsplit4(const float* __restrict__ w0, const float* __restrict__ w1,
              const float* __restrict__ w2, const float* __restrict__ w3,
              __nv_bfloat16* __restrict__ hi4, __nv_bfloat16* __restrict__ lo4) {
    __shared__ float t[32][33];
    const int z = blockIdx.z;
    const float* W = (z == 0) ? w0 : (z == 1) ? w1 : (z == 2) ? w2 : w3;
    __nv_bfloat16* hi = hi4 + (size_t)z * DM_ * DM_;
    __nv_bfloat16* lo = lo4 + (size_t)z * DM_ * DM_;
    const int n0 = blockIdx.x * 32;
    const int k0 = blockIdx.y * 32;
    const int tx = threadIdx.x, ty = threadIdx.y;
#pragma unroll
    for (int i = 0; i < 4; ++i)
        t[ty + i * 8][tx] = W[(size_t)(k0 + ty + i * 8) * DM_ + n0 + tx];
    __syncthreads();
#pragma unroll
    for (int i = 0; i < 4; ++i) {
        float v = t[tx][ty + i * 8];
        __nv_bfloat16 h = __float2bfloat16_rn(v);
        __nv_bfloat16 l = __float2bfloat16_rn(v - __bfloat162float(h));
        size_t o = (size_t)(n0 + ty + i * 8) * DM_ + k0 + tx;
        hi[o] = h;
        lo[o] = l;
    }
}

// ===========================================================================
// HMMA GEMM (bf16 hi/lo x3): 3-stage cp.async ring, 1 sync/ktile,
// XOR-swizzled 64B rows. 2 CTAs/SM.
// ===========================================================================
#define BM 128
#define BN 128
#define BK 32
#define NKT (DM_ / BK)            // 32
#define GT_TILE 8192              // 128 rows * 64B
#define GT_STAGE (4 * GT_TILE)    // 32768: Ahi,Alo,Bhi,Blo
#define GEMM_SMEM (3 * GT_STAGE)  // 98304

__device__ __forceinline__ void load_ktile(uint32_t sb, int kt, int stage,
                                           const __nv_bfloat16* Ahi,
                                           const __nv_bfloat16* Alo,
                                           const __nv_bfloat16* Bhi,
                                           const __nv_bfloat16* Blo,
                                           int rowBase, int colBase) {
    const int tid = threadIdx.x;
    const uint32_t base = sb + stage * GT_STAGE;
    const __nv_bfloat16* srcs[4] = {
        Ahi + (size_t)rowBase * DM_ + kt * BK,
        Alo + (size_t)rowBase * DM_ + kt * BK,
        Bhi + (size_t)colBase * DM_ + kt * BK,
        Blo + (size_t)colBase * DM_ + kt * BK};
#pragma unroll
    for (int t = 0; t < 4; ++t) {
#pragma unroll
        for (int i = 0; i < 2; ++i) {
            int c = tid + i * 256;          // 0..511
            int r = c >> 2, ch = c & 3;
            cp16(base + t * GT_TILE + r * 64 + SWZ64B(r, ch),
                 srcs[t] + (size_t)r * DM_ + ch * 8);
        }
    }
}

__device__ __forceinline__ void gemm_body(
    const __nv_bfloat16* __restrict__ Ahi, const __nv_bfloat16* __restrict__ Alo,
    const __nv_bfloat16* __restrict__ Bhi, const __nv_bfloat16* __restrict__ Blo,
    const float* __restrict__ bias, float* __restrict__ C,
    __nv_bfloat16* __restrict__ Chi, __nv_bfloat16* __restrict__ Clo,
    char* smem) {
    const uint32_t sb = smem_u32(smem);
    const int tid  = threadIdx.x;
    const int wid  = tid >> 5;
    const int lane = tid & 31;
    const int rowBase = blockIdx.y * BM;
    const int colBase = blockIdx.x * BN;

    const int mbase = (wid >> 1) * 32;
    const int nbase = (wid & 1) * 64;

    float acc[2][8][4];
#pragma unroll
    for (int i = 0; i < 2; ++i)
#pragma unroll
        for (int j = 0; j < 8; ++j)
#pragma unroll
            for (int q = 0; q < 4; ++q) acc[i][j][q] = 0.f;

    load_ktile(sb, 0, 0, Ahi, Alo, Bhi, Blo, rowBase, colBase);
    CP_COMMIT();
    load_ktile(sb, 1, 1, Ahi, Alo, Bhi, Blo, rowBase, colBase);
    CP_COMMIT();

    const int a_row = lane & 15;
    const int a_kb  = lane >> 4;            // k-half bit
    const int b_row = ((lane >> 4) & 1) * 8 + (lane & 7);
    const int b_kb  = (lane >> 3) & 1;

    int cur = 0, pf = 2;
    for (int kt = 0; kt < NKT; ++kt) {
        if (kt + 1 < NKT) { CP_WAIT(1); } else { CP_WAIT(0); }
        __syncthreads();
        if (kt + 2 < NKT) {
            load_ktile(sb, kt + 2, pf, Ahi, Alo, Bhi, Blo, rowBase, colBase);
            CP_COMMIT();
        }

        const uint32_t st = sb + cur * GT_STAGE;
#pragma unroll
        for (int s = 0; s < 2; ++s) {
            uint32_t ah[2][4], al[2][4];
#pragma unroll
            for (int i = 0; i < 2; ++i) {
                int row = mbase + i * 16 + a_row;
                uint32_t off = row * 64 + SWZ64B(row, s * 2 + a_kb);
                ldmx4(ah[i], st + 0 * GT_TILE + off);
                ldmx4(al[i], st + 1 * GT_TILE + off);
            }
#pragma unroll
            for (int jp = 0; jp < 4; ++jp) {
                int row = nbase + jp * 16 + b_row;
                uint32_t off = row * 64 + SWZ64B(row, s * 2 + b_kb);
                uint32_t th[4], tl[4];
                ldmx4(th, st + 2 * GT_TILE + off);
                ldmx4(tl, st + 3 * GT_TILE + off);
                uint32_t b0h[2] = {th[0], th[1]}, b1h[2] = {th[2], th[3]};
                uint32_t b0l[2] = {tl[0], tl[1]}, b1l[2] = {tl[2], tl[3]};
#pragma unroll
                for (int i = 0; i < 2; ++i) {
                    // interleave across the two accumulators to break RAW chains
                    mma_bf16(acc[i][jp * 2],     ah[i], b0h);
                    mma_bf16(acc[i][jp * 2 + 1], ah[i], b1h);
                    mma_bf16(acc[i][jp * 2],     ah[i], b0l);
                    mma_bf16(acc[i][jp * 2 + 1], ah[i], b1l);
                    mma_bf16(acc[i][jp * 2],     al[i], b0h);
                    mma_bf16(acc[i][jp * 2 + 1], al[i], b1h);
                }
            }
        }
        cur = inc3(cur);
        pf  = inc3(pf);
    }

#pragma unroll
    for (int i = 0; i < 2; ++i) {
        const int r0 = rowBase + mbase + i * 16 + (lane >> 2);
#pragma unroll
        for (int j = 0; j < 8; ++j) {
            const int col = colBase + nbase + j * 8 + (lane & 3) * 2;
            const float b0 = bias[col], b1 = bias[col + 1];
            float f0 = acc[i][j][0] + b0, f1 = acc[i][j][1] + b1;
            float f2 = acc[i][j][2] + b0, f3 = acc[i][j][3] + b1;
            if (C) {
                *(float2*)(C + (size_t)r0 * DM_ + col)       = make_float2(f0, f1);
                *(float2*)(C + (size_t)(r0 + 8) * DM_ + col) = make_float2(f2, f3);
            } else {
                uint32_t h01 = cvt_bf16x2(f1, f0);
                uint32_t h23 = cvt_bf16x2(f3, f2);
                float r0f = f0 - __uint_as_float(h01 << 16);
                float r1f = f1 - __uint_as_float(h01 & 0xFFFF0000u);
                float r2f = f2 - __uint_as_float(h23 << 16);
                float r3f = f3 - __uint_as_float(h23 & 0xFFFF0000u);
                uint32_t l01 = cvt_bf16x2(r1f, r0f);
                uint32_t l23 = cvt_bf16x2(r3f, r2f);
                *(uint32_t*)(Chi + (size_t)r0 * DM_ + col)       = h01;
                *(uint32_t*)(Chi + (size_t)(r0 + 8) * DM_ + col) = h23;
                *(uint32_t*)(Clo + (size_t)r0 * DM_ + col)       = l01;
                *(uint32_t*)(Clo + (size_t)(r0 + 8) * DM_ + col) = l23;
            }
        }
    }
}

__global__ __launch_bounds__(256, 2)
void gemm_qkv(const __nv_bfloat16* __restrict__ Ah0, const __nv_bfloat16* __restrict__ Al0,
              const __nv_bfloat16* __restrict__ Ah1, const __nv_bfloat16* __restrict__ Al1,
              const __nv_bfloat16* __restrict__ Ah2, const __nv_bfloat16* __restrict__ Al2,
              const __nv_bfloat16* __restrict__ Wh4, const __nv_bfloat16* __restrict__ Wl4,
              const float* __restrict__ b0, const float* __restrict__ b1,
              const float* __restrict__ b2,
              __nv_bfloat16* __restrict__ Ch0, __nv_bfloat16* __restrict__ Cl0,
              __nv_bfloat16* __restrict__ Ch1, __nv_bfloat16* __restrict__ Cl1,
              __nv_bfloat16* __restrict__ Ch2, __nv_bfloat16* __restrict__ Cl2) {
    extern __shared__ char smem[];
    const int z = blockIdx.z;
    const __nv_bfloat16* Ah = (z == 0) ? Ah0 : (z == 1) ? Ah1 : Ah2;
    const __nv_bfloat16* Al = (z == 0) ? Al0 : (z == 1) ? Al1 : Al2;
    const float* bias = (z == 0) ? b0 : (z == 1) ? b1 : b2;
    __nv_bfloat16* Ch = (z == 0) ? Ch0 : (z == 1) ? Ch1 : Ch2;
    __nv_bfloat16* Cl = (z == 0) ? Cl0 : (z == 1) ? Cl1 : Cl2;
    gemm_body(Ah, Al, Wh4 + (size_t)z * DM_ * DM_, Wl4 + (size_t)z * DM_ * DM_,
              bias, nullptr, Ch, Cl, smem);
}

__global__ __launch_bounds__(256, 2)
void gemm_o(const __nv_bfloat16* __restrict__ Ahi, const __nv_bfloat16* __restrict__ Alo,
            const __nv_bfloat16* __restrict__ Whi, const __nv_bfloat16* __restrict__ Wlo,
            const float* __restrict__ bias, float* __restrict__ C) {
    extern __shared__ char smem[];
    gemm_body(Ahi, Alo, Whi, Wlo, bias, C, nullptr, nullptr, smem);
}

// ===========================================================================
// Flash attention v4: 3-stage KV ring, 1 sync/tile, XOR-swizzled 128B rows.
// CTA: 128 q-rows, 8 warps each owning 16 rows. 2 CTAs/SM.
// ===========================================================================
#define FTT  8192                  // 64 rows * 128B
#define FSTG (4 * FTT)             // Khi,Klo,Vhi,Vlo = 32768
#define FQT  16384                 // 128 rows * 128B
#define FA4_SMEM (3 * FSTG + FQT)  // 114688

#define C2F 0.1803368801111204f    // log2(e)/8 (Dh=64 scale folded into exp2)

__device__ __forceinline__ void fa_load(uint32_t dstBase,
    const __nv_bfloat16* Khi, const __nv_bfloat16* Klo,
    const __nv_bfloat16* Vhi, const __nv_bfloat16* Vlo,
    size_t rowStart, int k0, int colOff) {
    const int tid = threadIdx.x;
    const __nv_bfloat16* srcs[4] = {
        Khi + (rowStart + k0) * DM_ + colOff,
        Klo + (rowStart + k0) * DM_ + colOff,
        Vhi + (rowStart + k0) * DM_ + colOff,
        Vlo + (rowStart + k0) * DM_ + colOff};
#pragma unroll
    for (int i = 0; i < 8; ++i) {
        int c = tid + i * 256;           // 0..2047
        int t = c >> 9, r = (c >> 3) & 63, ch = c & 7;
        cp16(dstBase + t * FTT + r * 128 + SWZ128B(r, ch),
             srcs[t] + (size_t)r * DM_ + ch * 8);
    }
}

__global__ __launch_bounds__(256, 2)
void flash_mma4(const __nv_bfloat16* __restrict__ Qhi,
                const __nv_bfloat16* __restrict__ Qlo,
                const __nv_bfloat16* __restrict__ Khi,
                const __nv_bfloat16* __restrict__ Klo,
                const __nv_bfloat16* __restrict__ Vhi,
                const __nv_bfloat16* __restrict__ Vlo,
                __nv_bfloat16* __restrict__ AOh,
                __nv_bfloat16* __restrict__ AOl) {
    extern __shared__ char smem[];
    const uint32_t sb = smem_u32(smem);
    const int tid = threadIdx.x, wid = tid >> 5, lane = tid & 31;
    const int bh = blockIdx.y, b = bh >> 4, h = bh & 15;
    const int q0 = blockIdx.x * 128;
    const size_t rowStart = (size_t)b * S_;
    const int colOff = h * DH_;

    const uint32_t sQlo = sb + 3 * FSTG;     // persistent Q-lo (16 KB)
    const uint32_t sQhiStage = sb + 2 * FSTG; // Q-hi staged in ring stage 2

    // ---- group A: Qhi -> stage2, Qlo -> persistent ----
    {
        const __nv_bfloat16* qh_src = Qhi + (rowStart + q0) * DM_ + colOff;
        const __nv_bfloat16* ql_src = Qlo + (rowStart + q0) * DM_ + colOff;
#pragma unroll
        for (int i = 0; i < 4; ++i) {
            int c = tid + i * 256;       // 0..1023: r 0..127, ch 0..7
            int r = c >> 3, ch = c & 7;
            uint32_t off = r * 128 + SWZ128B(r, ch);
            cp16(sQhiStage + off, qh_src + (size_t)r * DM_ + ch * 8);
            cp16(sQlo      + off, ql_src + (size_t)r * DM_ + ch * 8);
        }
    }
    CP_COMMIT();
    fa_load(sb + 0 * FSTG, Khi, Klo, Vhi, Vlo, rowStart, 0, colOff);   // group B
    CP_COMMIT();
    fa_load(sb + 1 * FSTG, Khi, Klo, Vhi, Vlo, rowStart, 64, colOff);  // group C
    CP_COMMIT();
    CP_WAIT(2);                          // group A (Q) complete
    __syncthreads();

    // fragment addressing
    const int a_row = lane & 15;
    const int a_kb  = lane >> 4;
    const int b_row = ((lane >> 4) & 1) * 8 + (lane & 7);
    const int b_kb  = (lane >> 3) & 1;
    const int v_k   = (lane & 7) + ((lane >> 3) & 1) * 8;
    const int v_db  = (lane >> 4) & 1;

    // ---- Q-hi fragments into registers ----
    uint32_t qh[4][4];
    const int qrow = 16 * wid + a_row;
#pragma unroll
    for (int ks = 0; ks < 4; ++ks)
        ldmx4(qh[ks], sQhiStage + qrow * 128 + SWZ128B(qrow, ks * 2 + a_kb));
    // NOTE: no sync needed here — the first loop-top sync protects stage 2
    // before any warp's prefetch overwrites it.

    float m0 = -1e30f, m1 = -1e30f, l0 = 0.f, l1 = 0.f;
    float o[8][4];
#pragma unroll
    for (int j = 0; j < 8; ++j)
#pragma unroll
        for (int q = 0; q < 4; ++q) o[j][q] = 0.f;

    int cur = 0, pf = 2;
    for (int jt = 0; jt < S_ / 64; ++jt) {
        if (jt + 1 < S_ / 64) { CP_WAIT(1); } else { CP_WAIT(0); }
        __syncthreads();                 // tile jt resident; stage pf free
        if (jt + 2 < S_ / 64) {
            fa_load(sb + pf * FSTG, Khi, Klo, Vhi, Vlo,
                    rowStart, (jt + 2) * 64, colOff);
            CP_COMMIT();
        }
        const uint32_t kvb = sb + cur * FSTG;

        // ---- scores: S = Q K^T (x3 hi/lo passes; Q-lo from smem) ----
        float s[8][4];
#pragma unroll
        for (int j = 0; j < 8; ++j)
#pragma unroll
            for (int q = 0; q < 4; ++q) s[j][q] = 0.f;

#pragma unroll
        for (int ks = 0; ks < 4; ++ks) {
            uint32_t ql[4];
            ldmx4(ql, sQlo + qrow * 128 + SWZ128B(qrow, ks * 2 + a_kb));
#pragma unroll
            for (int ntp = 0; ntp < 4; ++ntp) {
                const int krow = ntp * 16 + b_row;
                const uint32_t off = krow * 128 + SWZ128B(krow, ks * 2 + b_kb);
                uint32_t th[4], tl[4];
                ldmx4(th, kvb + off);
                ldmx4(tl, kvb + FTT + off);
                uint32_t k0h[2] = {th[0], th[1]}, k1h[2] = {th[2], th[3]};
                uint32_t k0l[2] = {tl[0], tl[1]}, k1l[2] = {tl[2], tl[3]};
                mma_bf16(s[2 * ntp],     qh[ks], k0h);
                mma_bf16(s[2 * ntp + 1], qh[ks], k1h);
                mma_bf16(s[2 * ntp],     qh[ks], k0l);
                mma_bf16(s[2 * ntp + 1], qh[ks], k1l);
                mma_bf16(s[2 * ntp],     ql, k0h);
                mma_bf16(s[2 * ntp + 1], ql, k1h);
            }
        }

        // ---- online softmax (warp-private rows; quad shuffles only) ----
        float rmax0 = -1e30f, rmax1 = -1e30f;
#pragma unroll
        for (int j = 0; j < 8; ++j) {
            rmax0 = fmaxf(rmax0, fmaxf(s[j][0], s[j][1]));
            rmax1 = fmaxf(rmax1, fmaxf(s[j][2], s[j][3]));
        }
        rmax0 = fmaxf(rmax0, __shfl_xor_sync(0xffffffffu, rmax0, 1));
        rmax0 = fmaxf(rmax0, __shfl_xor_sync(0xffffffffu, rmax0, 2));
        rmax1 = fmaxf(rmax1, __shfl_xor_sync(0xffffffffu, rmax1, 1));
        rmax1 = fmaxf(rmax1, __shfl_xor_sync(0xffffffffu, rmax1, 2));
        const float m0n = fmaxf(m0, rmax0);
        const float m1n = fmaxf(m1, rmax1);
        const float c0 = ex2f((m0 - m0n) * C2F);
        const float c1 = ex2f((m1 - m1n) * C2F);
        m0 = m0n; m1 = m1n;
#pragma unroll
        for (int j = 0; j < 8; ++j) {
            o[j][0] *= c0; o[j][1] *= c0;
            o[j][2] *= c1; o[j][3] *= c1;
        }
        float sum0 = 0.f, sum1 = 0.f;
#pragma unroll
        for (int j = 0; j < 8; ++j) {
            s[j][0] = ex2f((s[j][0] - m0) * C2F);
            s[j][1] = ex2f((s[j][1] - m0) * C2F);
            s[j][2] = ex2f((s[j][2] - m1) * C2F);
            s[j][3] = ex2f((s[j][3] - m1) * C2F);
            sum0 += s[j][0] + s[j][1];
            sum1 += s[j][2] + s[j][3];
        }
        sum0 += __shfl_xor_sync(0xffffffffu, sum0, 1);
        sum0 += __shfl_xor_sync(0xffffffffu, sum0, 2);
        sum1 += __shfl_xor_sync(0xffffffffu, sum1, 1);
        sum1 += __shfl_xor_sync(0xffffffffu, sum1, 2);
        l0 = l0 * c0 + sum0;
        l1 = l1 * c1 + sum1;

        // ---- pack P into bf16 hi/lo A-fragments ----
        uint32_t PHa[8], PHb[8], PLa[8], PLb[8];
#pragma unroll
        for (int j = 0; j < 8; ++j) {
            PHa[j] = cvt_bf16x2(s[j][1], s[j][0]);
            PHb[j] = cvt_bf16x2(s[j][3], s[j][2]);
            float ra0 = s[j][0] - __uint_as_float(PHa[j] << 16);
            float ra1 = s[j][1] - __uint_as_float(PHa[j] & 0xFFFF0000u);
            float rb0 = s[j][2] - __uint_as_float(PHb[j] << 16);
            float rb1 = s[j][3] - __uint_as_float(PHb[j] & 0xFFFF0000u);
            PLa[j] = cvt_bf16x2(ra1, ra0);
            PLb[j] = cvt_bf16x2(rb1, rb0);
        }

        // ---- O += P @ V (x3 hi/lo passes, V^T frags via ldmatrix.trans) ----
#pragma unroll
        for (int ks = 0; ks < 4; ++ks) {
            uint32_t ah[4] = {PHa[2 * ks], PHb[2 * ks],
                              PHa[2 * ks + 1], PHb[2 * ks + 1]};
            uint32_t al[4] = {PLa[2 * ks], PLb[2 * ks],
                              PLa[2 * ks + 1], PLb[2 * ks + 1]};
            const int vrow = 16 * ks + v_k;
#pragma unroll
            for (int dt = 0; dt < 4; ++dt) {
                const uint32_t off = vrow * 128 + SWZ128B(vrow, dt * 2 + v_db);
                uint32_t vh[4], vl[4];
                ldmx4t(vh, kvb + 2 * FTT + off);
                ldmx4t(vl, kvb + 3 * FTT + off);
                uint32_t b0h[2] = {vh[0], vh[1]}, b1h[2] = {vh[2], vh[3]};
                uint32_t b0l[2] = {vl[0], vl[1]}, b1l[2] = {vl[2], vl[3]};
                mma_bf16(o[2 * dt],     ah, b0h);
                mma_bf16(o[2 * dt + 1], ah, b1h);
                mma_bf16(o[2 * dt],     ah, b0l);
                mma_bf16(o[2 * dt + 1], ah, b1l);
                mma_bf16(o[2 * dt],     al, b0h);
                mma_bf16(o[2 * dt + 1], al, b1h);
            }
        }
        cur = inc3(cur);
        pf  = inc3(pf);
    }

    // ---- normalize, split to bf16 hi/lo, write ----
    const float i0 = 1.f / l0, i1 = 1.f / l1;
    const size_t row0 = rowStart + q0 + 16 * wid + (lane >> 2);
    const size_t row1 = row0 + 8;
#pragma unroll
    for (int j = 0; j < 8; ++j) {
        const int col = colOff + j * 8 + (lane & 3) * 2;
        float f0 = o[j][0] * i0, f1 = o[j][1] * i0;
        float f2 = o[j][2] * i1, f3 = o[j][3] * i1;
        uint32_t h01 = cvt_bf16x2(f1, f0);
        uint32_t h23 = cvt_bf16x2(f3, f2);
        float r0f = f0 - __uint_as_float(h01 << 16);
        float r1f = f1 - __uint_as_float(h01 & 0xFFFF0000u);
        float r2f = f2 - __uint_as_float(h23 << 16);
        float r3f = f3 - __uint_as_float(h23 & 0xFFFF0000u);
        uint32_t l01 = cvt_bf16x2(r1f, r0f);
        uint32_t l23 = cvt_bf16x2(r3f, r2f);
        *(uint32_t*)(AOh + row0 * DM_ + col) = h01;
        *(uint32_t*)(AOh + row1 * DM_ + col) = h23;
        *(uint32_t*)(AOl + row0 * DM_ + col) = l01;
        *(uint32_t*)(AOl + row1 * DM_ + col) = l23;
    }
}

// ===========================================================================
// Launch
// ===========================================================================
extern "C" void kernel_launch(void* const* d_in, const int* in_sizes, int n_in,
                              void* d_out, int out_size)
{
    const float* query = (const float*)d_in[0];
    const float* key   = (const float*)d_in[1];
    const float* value = (const float*)d_in[2];
    const float* Wq    = (const float*)d_in[3];
    const float* bq    = (const float*)d_in[4];
    const float* Wk    = (const float*)d_in[5];
    const float* bk    = (const float*)d_in[6];
    const float* Wv    = (const float*)d_in[7];
    const float* bv    = (const float*)d_in[8];
    const float* Wo    = (const float*)d_in[9];
    const float* bo    = (const float*)d_in[10];
    float* out = (float*)d_out;

    __nv_bfloat16 *pIh, *pIl, *pWh, *pWl;
    __nv_bfloat16 *pQh, *pQl, *pKh, *pKl, *pVh, *pVl, *pAOh, *pAOl;
    cudaGetSymbolAddress((void**)&pIh,  g_Ih);
    cudaGetSymbolAddress((void**)&pIl,  g_Il);
    cudaGetSymbolAddress((void**)&pWh,  g_W4h);
    cudaGetSymbolAddress((void**)&pWl,  g_W4l);
    cudaGetSymbolAddress((void**)&pQh,  g_Qh);
    cudaGetSymbolAddress((void**)&pQl,  g_Ql);
    cudaGetSymbolAddress((void**)&pKh,  g_Kh);
    cudaGetSymbolAddress((void**)&pKl,  g_Kl);
    cudaGetSymbolAddress((void**)&pVh,  g_Vh);
    cudaGetSymbolAddress((void**)&pVl,  g_Vl);
    cudaGetSymbolAddress((void**)&pAOh, g_AOh);
    cudaGetSymbolAddress((void**)&pAOl, g_AOl);

    const size_t NTOK = (size_t)ROWS_ * DM_;

    static bool attrs_set = false;
    if (!attrs_set) {
        cudaFuncSetAttribute(gemm_qkv, cudaFuncAttributeMaxDynamicSharedMemorySize, GEMM_SMEM);
        cudaFuncSetAttribute(gemm_o,   cudaFuncAttributeMaxDynamicSharedMemorySize, GEMM_SMEM);
        cudaFuncSetAttribute(flash_mma4, cudaFuncAttributeMaxDynamicSharedMemorySize, FA4_SMEM);
        attrs_set = true;
    }

    const int n4 = ROWS_ * DM_ / 4;

    // 1) split all three inputs
    split3<<<dim3((n4 + 255) / 256, 3), 256>>>(
        (const float4*)query, (const float4*)key, (const float4*)value,
        pIh + 0 * NTOK, pIl + 0 * NTOK,
        pIh + 1 * NTOK, pIl + 1 * NTOK,
        pIh + 2 * NTOK, pIl + 2 * NTOK, n4);

    // 2) split+transpose all four weights
    wtsplit4<<<dim3(32, 32, 4), dim3(32, 8)>>>(Wq, Wk, Wv, Wo, pWh, pWl);

    // 3) Q,K,V projections (batched, epilogue -> bf16 hi/lo)
    gemm_qkv<<<dim3(DM_ / BN, ROWS_ / BM, 3), 256, GEMM_SMEM>>>(
        pIh + 0 * NTOK, pIl + 0 * NTOK,
        pIh + 1 * NTOK, pIl + 1 * NTOK,
        pIh + 2 * NTOK, pIl + 2 * NTOK,
        pWh, pWl, bq, bk, bv,
        pQh, pQl, pKh, pKl, pVh, pVl);

    // 4) attention (writes bf16 hi/lo)
    flash_mma4<<<dim3(S_ / 128, B_ * NH_), 256, FA4_SMEM>>>(
        pQh, pQl, pKh, pKl, pVh, pVl, pAOh, pAOl);

    // 5) output projection (fp32 result)
    gemm_o<<<dim3(DM_ / BN, ROWS_ / BM), 256, GEMM_SMEM>>>(
        pAOh, pAOl,
        pWh + 3 * (size_t)DM_ * DM_, pWl + 3 * (size_t)DM_ * DM_,
        bo, out);
}